// round 1
// baseline (speedup 1.0000x reference)
#include <cuda_runtime.h>
#include <cstdint>

// ---------------------------------------------------------------------------
// Problem constants: B=8, L=4096, D=1024, H=8, DH=128, WIN=128
//   M = B*L = 32768 rows for all big GEMMs.
// ---------------------------------------------------------------------------

// Scratch (static __device__ globals; allocation inside kernel_launch is banned)
__device__ float  g_ada [8 * 6144];          // modulation vectors
__device__ float  g_x1  [33554432];          // modulated input 1 (32768 x 1024)
__device__ float  g_qkv [100663296];         // qkv (32768 x 3072)
__device__ float  g_o   [33554432];          // attention out (32768 x 1024)
__device__ float  g_res [33554432];          // residual after MSA (32768 x 1024)
__device__ float  g_h   [33554432];          // modulated input 2 (32768 x 1024)
__device__ float  g_h1  [134217728];         // ff hidden (32768 x 4096)
__device__ float2 g_rope[8192];              // (sin, cos) table [128 pos][64 freq]

// ---------------------------------------------------------------------------
// helpers
// ---------------------------------------------------------------------------
__device__ __forceinline__ float ftf(float x) {
    // round-to-nearest tf32 (keeps accuracy ~2^-11 instead of truncation)
    uint32_t u;
    asm("cvt.rna.tf32.f32 %0, %1;" : "=r"(u) : "f"(x));
    return __uint_as_float(u);
}

__device__ __forceinline__ void mma8(float* d, const uint32_t* a, const uint32_t* b) {
    asm volatile(
        "mma.sync.aligned.m16n8k8.row.col.f32.tf32.tf32.f32 "
        "{%0,%1,%2,%3}, {%4,%5,%6,%7}, {%8,%9}, {%0,%1,%2,%3};"
        : "+f"(d[0]), "+f"(d[1]), "+f"(d[2]), "+f"(d[3])
        : "r"(a[0]), "r"(a[1]), "r"(a[2]), "r"(a[3]), "r"(b[0]), "r"(b[1]));
}

__device__ __forceinline__ float gelu_tanh(float x) {
    // jax.nn.gelu default (approximate=True)
    float u = 0.7978845608028654f * (x + 0.044715f * x * x * x);
    return 0.5f * x * (1.f + tanhf(u));
}

// ---------------------------------------------------------------------------
// Kernel 1: ada = silu(context) @ W_ada + b_ada       (8 x 1024) @ (1024 x 6144)
// 24 blocks x 256 threads; each thread owns one output column for all 8 batches
// ---------------------------------------------------------------------------
__global__ void __launch_bounds__(256) ada_kernel(
    const float* __restrict__ ctx, const float* __restrict__ W,
    const float* __restrict__ bias, float* __restrict__ ada)
{
    __shared__ float sctx[8 * 1024];
    for (int i = threadIdx.x; i < 8192; i += 256) {
        float c = ctx[i];
        sctx[i] = c / (1.f + __expf(-c));   // silu
    }
    __syncthreads();

    const int col = blockIdx.x * 256 + threadIdx.x;
    float acc[8] = {0.f, 0.f, 0.f, 0.f, 0.f, 0.f, 0.f, 0.f};
    for (int k = 0; k < 1024; k++) {
        float w = W[(size_t)k * 6144 + col];
        #pragma unroll
        for (int b = 0; b < 8; b++) acc[b] += sctx[b * 1024 + k] * w;
    }
    float bv = bias[col];
    #pragma unroll
    for (int b = 0; b < 8; b++) ada[b * 6144 + col] = acc[b] + bv;
}

// ---------------------------------------------------------------------------
// Kernel 2: rope table   tab[pos*64+i] = (sin, cos)(pos * 10000^(-2i/128))
// ---------------------------------------------------------------------------
__global__ void rope_kernel(float2* __restrict__ tab)
{
    int idx = blockIdx.x * 256 + threadIdx.x;
    if (idx < 8192) {
        int pos = idx >> 6;
        int i   = idx & 63;
        float freq = powf(10000.f, -(float)(2 * i) / 128.f);
        float ang  = (float)pos * freq;
        tab[idx] = make_float2(sinf(ang), cosf(ang));
    }
}

// ---------------------------------------------------------------------------
// Kernel 3: y = rmsnorm(x, scale) * (1 + sc) + sh   (one block per row of 1024)
// ---------------------------------------------------------------------------
__global__ void __launch_bounds__(256) norm_mod(
    const float* __restrict__ x, const float* __restrict__ scale,
    const float* __restrict__ ada, int shOff, int scOff,
    float* __restrict__ y)
{
    const int row = blockIdx.x;
    const int b   = row >> 12;
    const float4 v = ((const float4*)(x + (size_t)row * 1024))[threadIdx.x];

    float ss = v.x * v.x + v.y * v.y + v.z * v.z + v.w * v.w;
    #pragma unroll
    for (int o = 16; o > 0; o >>= 1) ss += __shfl_xor_sync(0xffffffffu, ss, o);
    __shared__ float ws[8];
    if ((threadIdx.x & 31) == 0) ws[threadIdx.x >> 5] = ss;
    __syncthreads();
    float tot = 0.f;
    #pragma unroll
    for (int i = 0; i < 8; i++) tot += ws[i];
    const float r = rsqrtf(tot * (1.f / 1024.f) + 1e-5f);

    const int c = threadIdx.x * 4;
    const float* ab = ada + b * 6144;
    const float4 s   = *(const float4*)(scale + c);
    const float4 sh  = *(const float4*)(ab + shOff + c);
    const float4 scm = *(const float4*)(ab + scOff + c);
    float4 o;
    o.x = v.x * r * s.x * (1.f + scm.x) + sh.x;
    o.y = v.y * r * s.y * (1.f + scm.y) + sh.y;
    o.z = v.z * r * s.z * (1.f + scm.z) + sh.z;
    o.w = v.w * r * s.w * (1.f + scm.w) + sh.w;
    ((float4*)(y + (size_t)row * 1024))[threadIdx.x] = o;
}

// ---------------------------------------------------------------------------
// Kernel 4: generic tf32 tensor-core GEMM, C[M,N] = A[M,K] @ B[K,N] + bias
//   BM=128 BN=128 BK=32; 256 threads = 8 warps (4x2); warp tile 32x64.
//   MODE 0: store.  MODE 1: gelu.  MODE 2: out = res + gate[b] * C.
//   All dims are multiples of the tile => no bounds checks.
// ---------------------------------------------------------------------------
#define GEMM_SMEM_BYTES ((2 * 128 * 36 + 2 * 32 * 136) * 4)

template <int MODE>
__global__ void __launch_bounds__(256) gemm_tf32(
    const float* __restrict__ A, const float* __restrict__ B,
    const float* __restrict__ bias, float* __restrict__ C,
    int N, int K,
    const float* __restrict__ res, const float* __restrict__ gate)
{
    extern __shared__ float smn[];
    float* As = smn;               // [2][128][36]
    float* Bs = smn + 2 * 4608;    // [2][ 32][136]

    const int tid  = threadIdx.x;
    const int lane = tid & 31;
    const int warp = tid >> 5;
    const int g    = lane >> 2, tig = lane & 3;
    const int wm   = warp & 3;       // 0..3  -> 32-row slab
    const int wn   = warp >> 2;      // 0..1  -> 64-col slab
    const int cm   = blockIdx.y * 128;
    const int cn   = blockIdx.x * 128;

    // gmem staging: each thread moves 4 float4 per operand per tile
    const int ar = tid >> 3;          // 0..31
    const int ac = (tid & 7) * 4;     // 0..28
    const int br = tid >> 5;          // 0..7
    const int bc = (tid & 31) * 4;    // 0..124

    float4 av[4], bv[4];
    auto loadG = [&](int kt) {
        const float* Ap = A + (size_t)(cm + ar) * K + kt * 32 + ac;
        #pragma unroll
        for (int p = 0; p < 4; p++) av[p] = *(const float4*)(Ap + (size_t)p * 32 * K);
        const float* Bp = B + (size_t)(kt * 32 + br) * N + cn + bc;
        #pragma unroll
        for (int p = 0; p < 4; p++) bv[p] = *(const float4*)(Bp + (size_t)p * 8 * N);
    };
    auto storeS = [&](int buf) {
        float* Ab = As + buf * 4608;
        #pragma unroll
        for (int p = 0; p < 4; p++) {
            float* dst = Ab + (ar + p * 32) * 36 + ac;
            dst[0] = ftf(av[p].x); dst[1] = ftf(av[p].y);
            dst[2] = ftf(av[p].z); dst[3] = ftf(av[p].w);
        }
        float* Bb = Bs + buf * 4352;
        #pragma unroll
        for (int p = 0; p < 4; p++) {
            float* dst = Bb + (br + p * 8) * 136 + bc;
            dst[0] = ftf(bv[p].x); dst[1] = ftf(bv[p].y);
            dst[2] = ftf(bv[p].z); dst[3] = ftf(bv[p].w);
        }
    };

    float acc[2][8][4];
    #pragma unroll
    for (int mt = 0; mt < 2; mt++)
        #pragma unroll
        for (int nt = 0; nt < 8; nt++)
            #pragma unroll
            for (int i = 0; i < 4; i++) acc[mt][nt][i] = 0.f;

    const int ktiles = K >> 5;
    loadG(0); storeS(0); __syncthreads();

    for (int kt = 0; kt < ktiles; kt++) {
        const int buf = kt & 1;
        if (kt + 1 < ktiles) loadG(kt + 1);

        const float* Ab = As + buf * 4608;
        const float* Bb = Bs + buf * 4352;
        #pragma unroll
        for (int ks = 0; ks < 4; ks++) {
            const int k0 = ks * 8 + tig;
            uint32_t a[2][4];
            #pragma unroll
            for (int mt = 0; mt < 2; mt++) {
                const int m = wm * 32 + mt * 16 + g;
                a[mt][0] = __float_as_uint(Ab[m * 36 + k0]);
                a[mt][1] = __float_as_uint(Ab[(m + 8) * 36 + k0]);
                a[mt][2] = __float_as_uint(Ab[m * 36 + k0 + 4]);
                a[mt][3] = __float_as_uint(Ab[(m + 8) * 36 + k0 + 4]);
            }
            #pragma unroll
            for (int nt = 0; nt < 8; nt++) {
                const int n = wn * 64 + nt * 8 + g;
                uint32_t b[2];
                b[0] = __float_as_uint(Bb[k0 * 136 + n]);
                b[1] = __float_as_uint(Bb[(k0 + 4) * 136 + n]);
                mma8(acc[0][nt], a[0], b);
                mma8(acc[1][nt], a[1], b);
            }
        }
        if (kt + 1 < ktiles) storeS((kt + 1) & 1);
        __syncthreads();
    }

    // epilogue
    const int bb = cm >> 12;   // batch index (4096 rows per batch; cm % 128 == 0)
    #pragma unroll
    for (int mt = 0; mt < 2; mt++) {
        const int row0 = cm + wm * 32 + mt * 16 + g;
        #pragma unroll
        for (int nt = 0; nt < 8; nt++) {
            const int col = cn + wn * 64 + nt * 8 + 2 * tig;
            const float bi0 = bias[col], bi1 = bias[col + 1];
            float v0 = acc[mt][nt][0] + bi0;
            float v1 = acc[mt][nt][1] + bi1;
            float v2 = acc[mt][nt][2] + bi0;
            float v3 = acc[mt][nt][3] + bi1;
            if (MODE == 1) {
                v0 = gelu_tanh(v0); v1 = gelu_tanh(v1);
                v2 = gelu_tanh(v2); v3 = gelu_tanh(v3);
            }
            if (MODE == 2) {
                const float g0 = gate[bb * 6144 + col];
                const float g1 = gate[bb * 6144 + col + 1];
                const float* r0 = res + (size_t)row0 * N + col;
                const float* r1 = res + (size_t)(row0 + 8) * N + col;
                v0 = r0[0] + g0 * v0;  v1 = r0[1] + g1 * v1;
                v2 = r1[0] + g0 * v2;  v3 = r1[1] + g1 * v3;
            }
            *(float2*)(C + (size_t)row0 * N + col)       = make_float2(v0, v1);
            *(float2*)(C + (size_t)(row0 + 8) * N + col) = make_float2(v2, v3);
        }
    }
}

// ---------------------------------------------------------------------------
// Kernel 5: windowed attention, one block per (window, head).
//   Q,K rope'd into smem -> scores = QK^T/sqrt(128) via tf32 mma ->
//   register softmax -> P to smem, V (transposed) to smem -> O = P@V -> gmem.
// ---------------------------------------------------------------------------
#define ATTN_SMEM_BYTES (2 * 128 * 132 * 4)

__global__ void __launch_bounds__(256) attn_kernel(
    const float* __restrict__ qkv, float* __restrict__ obuf,
    const float2* __restrict__ rope)
{
    extern __shared__ float smn[];
    float* Qs = smn;               // [128][132]  Q, later P
    float* Ks = smn + 128 * 132;   // [128][132]  K, later V^T

    const int tid  = threadIdx.x;
    const int lane = tid & 31, warp = tid >> 5;
    const int g    = lane >> 2, tig = lane & 3;
    const int h    = blockIdx.x & 7;
    const int w    = blockIdx.x >> 3;
    const size_t rowbase = (size_t)w * 128;

    // load Q, K with rope (tf32-rounded)
    for (int idx = tid; idx < 16384; idx += 256) {
        const int i = idx >> 7, d = idx & 127;
        const float* base = qkv + (rowbase + i) * 3072 + h * 128;
        const float2 sc = rope[i * 64 + (d >> 1)];
        const float q  = base[d];
        const float qr = (d < 64) ? -base[d + 64] : base[d - 64];
        Qs[i * 132 + d] = ftf(q * sc.y + qr * sc.x);
        const float* kb = base + 1024;
        const float kk  = kb[d];
        const float kr  = (d < 64) ? -kb[d + 64] : kb[d - 64];
        Ks[i * 132 + d] = ftf(kk * sc.y + kr * sc.x);
    }
    __syncthreads();

    // scores: warp owns rows [warp*16, warp*16+16)
    float acc[16][4];
    #pragma unroll
    for (int nt = 0; nt < 16; nt++)
        #pragma unroll
        for (int i = 0; i < 4; i++) acc[nt][i] = 0.f;

    const int m0 = warp * 16 + g;
    #pragma unroll
    for (int ks = 0; ks < 16; ks++) {
        const int k0 = ks * 8 + tig;
        uint32_t a[4];
        a[0] = __float_as_uint(Qs[m0 * 132 + k0]);
        a[1] = __float_as_uint(Qs[(m0 + 8) * 132 + k0]);
        a[2] = __float_as_uint(Qs[m0 * 132 + k0 + 4]);
        a[3] = __float_as_uint(Qs[(m0 + 8) * 132 + k0 + 4]);
        #pragma unroll
        for (int nt = 0; nt < 16; nt++) {
            const int n = nt * 8 + g;
            uint32_t b[2];
            b[0] = __float_as_uint(Ks[n * 132 + k0]);
            b[1] = __float_as_uint(Ks[n * 132 + k0 + 4]);
            mma8(acc[nt], a, b);
        }
    }

    // softmax (rows m0 and m0+8 live in this thread + 3 siblings sharing g)
    const float scl = 0.08838834764831845f;  // 1/sqrt(128)
    float mx0 = -1e30f, mx1 = -1e30f;
    #pragma unroll
    for (int nt = 0; nt < 16; nt++) {
        acc[nt][0] *= scl; acc[nt][1] *= scl; acc[nt][2] *= scl; acc[nt][3] *= scl;
        mx0 = fmaxf(mx0, fmaxf(acc[nt][0], acc[nt][1]));
        mx1 = fmaxf(mx1, fmaxf(acc[nt][2], acc[nt][3]));
    }
    mx0 = fmaxf(mx0, __shfl_xor_sync(0xffffffffu, mx0, 1));
    mx0 = fmaxf(mx0, __shfl_xor_sync(0xffffffffu, mx0, 2));
    mx1 = fmaxf(mx1, __shfl_xor_sync(0xffffffffu, mx1, 1));
    mx1 = fmaxf(mx1, __shfl_xor_sync(0xffffffffu, mx1, 2));

    float s0 = 0.f, s1 = 0.f;
    #pragma unroll
    for (int nt = 0; nt < 16; nt++) {
        acc[nt][0] = __expf(acc[nt][0] - mx0);
        acc[nt][1] = __expf(acc[nt][1] - mx0);
        acc[nt][2] = __expf(acc[nt][2] - mx1);
        acc[nt][3] = __expf(acc[nt][3] - mx1);
        s0 += acc[nt][0] + acc[nt][1];
        s1 += acc[nt][2] + acc[nt][3];
    }
    s0 += __shfl_xor_sync(0xffffffffu, s0, 1);
    s0 += __shfl_xor_sync(0xffffffffu, s0, 2);
    s1 += __shfl_xor_sync(0xffffffffu, s1, 1);
    s1 += __shfl_xor_sync(0xffffffffu, s1, 2);
    const float i0 = 1.f / s0, i1 = 1.f / s1;

    // store probabilities into Qs (only this warp's rows -> no cross-warp race)
    #pragma unroll
    for (int nt = 0; nt < 16; nt++) {
        const int c = nt * 8 + 2 * tig;
        Qs[m0 * 132 + c]           = ftf(acc[nt][0] * i0);
        Qs[m0 * 132 + c + 1]       = ftf(acc[nt][1] * i0);
        Qs[(m0 + 8) * 132 + c]     = ftf(acc[nt][2] * i1);
        Qs[(m0 + 8) * 132 + c + 1] = ftf(acc[nt][3] * i1);
    }
    __syncthreads();   // everyone done reading K (and P store done)

    // V transposed into Ks:  Ks[d][j] = V[j][d]
    for (int idx = tid; idx < 16384; idx += 256) {
        const int j = idx >> 7, d = idx & 127;
        Ks[d * 132 + j] = ftf(qkv[(rowbase + j) * 3072 + 2048 + h * 128 + d]);
    }
    __syncthreads();

    // O = P @ V
    #pragma unroll
    for (int nt = 0; nt < 16; nt++)
        #pragma unroll
        for (int i = 0; i < 4; i++) acc[nt][i] = 0.f;

    #pragma unroll
    for (int ks = 0; ks < 16; ks++) {
        const int k0 = ks * 8 + tig;
        uint32_t a[4];
        a[0] = __float_as_uint(Qs[m0 * 132 + k0]);
        a[1] = __float_as_uint(Qs[(m0 + 8) * 132 + k0]);
        a[2] = __float_as_uint(Qs[m0 * 132 + k0 + 4]);
        a[3] = __float_as_uint(Qs[(m0 + 8) * 132 + k0 + 4]);
        #pragma unroll
        for (int nt = 0; nt < 16; nt++) {
            const int n = nt * 8 + g;      // output head-dim
            uint32_t b[2];
            b[0] = __float_as_uint(Ks[n * 132 + k0]);
            b[1] = __float_as_uint(Ks[n * 132 + k0 + 4]);
            mma8(acc[nt], a, b);
        }
    }

    // write O: obuf[row][h*128 + d]
    #pragma unroll
    for (int nt = 0; nt < 16; nt++) {
        const int col = h * 128 + nt * 8 + 2 * tig;
        *(float2*)(obuf + (rowbase + m0) * 1024 + col)     = make_float2(acc[nt][0], acc[nt][1]);
        *(float2*)(obuf + (rowbase + m0 + 8) * 1024 + col) = make_float2(acc[nt][2], acc[nt][3]);
    }
}

// ---------------------------------------------------------------------------
// host launcher
// ---------------------------------------------------------------------------
extern "C" void kernel_launch(void* const* d_in, const int* in_sizes, int n_in,
                              void* d_out, int out_size)
{
    const float* group_x = (const float*)d_in[0];
    const float* context = (const float*)d_in[1];
    const float* W_ada   = (const float*)d_in[2];
    const float* b_ada   = (const float*)d_in[3];
    const float* scale1  = (const float*)d_in[4];
    const float* W_qkv   = (const float*)d_in[5];
    const float* b_qkv   = (const float*)d_in[6];
    const float* W_out   = (const float*)d_in[7];
    const float* b_out   = (const float*)d_in[8];
    const float* scale2  = (const float*)d_in[9];
    const float* W_ff1   = (const float*)d_in[10];
    const float* b_ff1   = (const float*)d_in[11];
    const float* W_ff2   = (const float*)d_in[12];
    const float* b_ff2   = (const float*)d_in[13];
    float* out = (float*)d_out;

    float *ada, *x1, *qkv, *obuf, *res2, *hbuf, *h1;
    float2* rope;
    cudaGetSymbolAddress((void**)&ada,  g_ada);
    cudaGetSymbolAddress((void**)&x1,   g_x1);
    cudaGetSymbolAddress((void**)&qkv,  g_qkv);
    cudaGetSymbolAddress((void**)&obuf, g_o);
    cudaGetSymbolAddress((void**)&res2, g_res);
    cudaGetSymbolAddress((void**)&hbuf, g_h);
    cudaGetSymbolAddress((void**)&h1,   g_h1);
    cudaGetSymbolAddress((void**)&rope, g_rope);

    cudaFuncSetAttribute(gemm_tf32<0>, cudaFuncAttributeMaxDynamicSharedMemorySize, GEMM_SMEM_BYTES);
    cudaFuncSetAttribute(gemm_tf32<1>, cudaFuncAttributeMaxDynamicSharedMemorySize, GEMM_SMEM_BYTES);
    cudaFuncSetAttribute(gemm_tf32<2>, cudaFuncAttributeMaxDynamicSharedMemorySize, GEMM_SMEM_BYTES);
    cudaFuncSetAttribute(attn_kernel,  cudaFuncAttributeMaxDynamicSharedMemorySize, ATTN_SMEM_BYTES);

    // 1. ada = silu(context) @ W_ada + b_ada
    ada_kernel<<<24, 256>>>(context, W_ada, b_ada, ada);
    // 2. rope sin/cos table
    rope_kernel<<<32, 256>>>(rope);
    // 3. x1 = rmsnorm(group_x, scale1) * (1 + sc_msa) + sh_msa
    norm_mod<<<32768, 256>>>(group_x, scale1, ada, 0, 1024, x1);
    // 4. qkv = x1 @ W_qkv + b_qkv
    gemm_tf32<0><<<dim3(24, 256), 256, GEMM_SMEM_BYTES>>>(x1, W_qkv, b_qkv, qkv,
                                                          3072, 1024, nullptr, nullptr);
    // 5. windowed attention (rope fused)
    attn_kernel<<<2048, 256, ATTN_SMEM_BYTES>>>(qkv, obuf, rope);
    // 6. res2 = group_x + g_msa * (obuf @ W_out + b_out)
    gemm_tf32<2><<<dim3(8, 256), 256, GEMM_SMEM_BYTES>>>(obuf, W_out, b_out, res2,
                                                         1024, 1024, group_x, ada + 2048);
    // 7. hbuf = rmsnorm(res2, scale2) * (1 + sc_mlp) + sh_mlp
    norm_mod<<<32768, 256>>>(res2, scale2, ada, 3072, 4096, hbuf);
    // 8. h1 = gelu(hbuf @ W_ff1 + b_ff1)
    gemm_tf32<1><<<dim3(32, 256), 256, GEMM_SMEM_BYTES>>>(hbuf, W_ff1, b_ff1, h1,
                                                          4096, 1024, nullptr, nullptr);
    // 9. out = res2 + g_mlp * (h1 @ W_ff2 + b_ff2)
    gemm_tf32<2><<<dim3(8, 256), 256, GEMM_SMEM_BYTES>>>(h1, W_ff2, b_ff2, out,
                                                         1024, 4096, res2, ada + 5120);
}

// round 3
// speedup vs baseline: 1.0153x; 1.0153x over previous
#include <cuda_runtime.h>
#include <cstdint>

// ---------------------------------------------------------------------------
// B=8, L=4096, D=1024, H=8, DH=128, WIN=128; M = 32768.
// Legacy mma.sync tf32 (tcgen05 unavailable: harness PTX target is compute_103).
// GEMM: CTA 256x128, 8 warps of 64x64, cp.async double-buffered staging,
// float2 fragment loads via logical-k permutation, pre-rounded/transposed W.
// ---------------------------------------------------------------------------

__device__ float  g_ada [8 * 6144];
__device__ float  g_x1  [33554432];
__device__ float  g_qkv [100663296];
__device__ float  g_o   [33554432];
__device__ float  g_res [33554432];
__device__ float  g_h   [33554432];
__device__ float  g_h1  [134217728];
__device__ float2 g_rope[8192];
// transposed + tf32-rounded weights
__device__ float  g_wqkv[3145728];   // [3072][1024]
__device__ float  g_wout[1048576];   // [1024][1024]
__device__ float  g_wff1[4194304];   // [4096][1024]
__device__ float  g_wff2[4194304];   // [1024][4096]

// ---------------------------------------------------------------------------
// helpers
// ---------------------------------------------------------------------------
__device__ __forceinline__ float ftf(float x) {
    uint32_t u;
    asm("cvt.rna.tf32.f32 %0, %1;" : "=r"(u) : "f"(x));
    return __uint_as_float(u);
}

__device__ __forceinline__ float gelu_tanh(float x) {
    float u = 0.7978845608028654f * (x + 0.044715f * x * x * x);
    return 0.5f * x * (1.f + tanhf(u));
}

__device__ __forceinline__ uint32_t smem_u32(const void* p) {
    uint32_t a;
    asm("{ .reg .u64 t; cvta.to.shared.u64 t, %1; cvt.u32.u64 %0, t; }" : "=r"(a) : "l"(p));
    return a;
}

__device__ __forceinline__ void mma8(float* d, const uint32_t* a, const uint32_t* b) {
    asm volatile(
        "mma.sync.aligned.m16n8k8.row.col.f32.tf32.tf32.f32 "
        "{%0,%1,%2,%3}, {%4,%5,%6,%7}, {%8,%9}, {%0,%1,%2,%3};"
        : "+f"(d[0]), "+f"(d[1]), "+f"(d[2]), "+f"(d[3])
        : "r"(a[0]), "r"(a[1]), "r"(a[2]), "r"(a[3]), "r"(b[0]), "r"(b[1]));
}

__device__ __forceinline__ void cp16(uint32_t dst, const float* src) {
    asm volatile("cp.async.cg.shared.global [%0], [%1], 16;" :: "r"(dst), "l"(src));
}
#define CP_COMMIT() asm volatile("cp.async.commit_group;" ::: "memory")
#define CP_WAIT1()  asm volatile("cp.async.wait_group 1;"  ::: "memory")
#define CP_WAIT0()  asm volatile("cp.async.wait_group 0;"  ::: "memory")

// ---------------------------------------------------------------------------
// Kernel 0: weight transpose + tf32 round:  Wt[n][k] = rna_tf32(W[k][n])
// ---------------------------------------------------------------------------
__global__ void __launch_bounds__(256) transpose_round(
    const float* __restrict__ W, float* __restrict__ Wt, int K, int N)
{
    __shared__ float t[32][33];
    const int kb = blockIdx.y * 32, nb = blockIdx.x * 32;
    const int tx = threadIdx.x, ty = threadIdx.y;   // 32 x 8
    #pragma unroll
    for (int i = 0; i < 4; i++)
        t[ty + 8 * i][tx] = ftf(W[(size_t)(kb + ty + 8 * i) * N + nb + tx]);
    __syncthreads();
    #pragma unroll
    for (int i = 0; i < 4; i++)
        Wt[(size_t)(nb + ty + 8 * i) * K + kb + tx] = t[tx][ty + 8 * i];
}

// ---------------------------------------------------------------------------
// Kernel 1: ada = silu(context) @ W_ada + b_ada
// ---------------------------------------------------------------------------
__global__ void __launch_bounds__(256) ada_kernel(
    const float* __restrict__ ctx, const float* __restrict__ W,
    const float* __restrict__ bias, float* __restrict__ ada)
{
    __shared__ float sctx[8 * 1024];
    for (int i = threadIdx.x; i < 8192; i += 256) {
        float c = ctx[i];
        sctx[i] = c / (1.f + __expf(-c));
    }
    __syncthreads();
    const int col = blockIdx.x * 256 + threadIdx.x;
    float acc[8] = {0, 0, 0, 0, 0, 0, 0, 0};
    for (int k = 0; k < 1024; k++) {
        float w = W[(size_t)k * 6144 + col];
        #pragma unroll
        for (int b = 0; b < 8; b++) acc[b] += sctx[b * 1024 + k] * w;
    }
    float bv = bias[col];
    #pragma unroll
    for (int b = 0; b < 8; b++) ada[b * 6144 + col] = acc[b] + bv;
}

// ---------------------------------------------------------------------------
// Kernel 2: rope table
// ---------------------------------------------------------------------------
__global__ void rope_kernel(float2* __restrict__ tab)
{
    int idx = blockIdx.x * 256 + threadIdx.x;
    if (idx < 8192) {
        int pos = idx >> 6;
        int i   = idx & 63;
        float freq = powf(10000.f, -(float)(2 * i) / 128.f);
        float ang  = (float)pos * freq;
        tab[idx] = make_float2(sinf(ang), cosf(ang));
    }
}

// ---------------------------------------------------------------------------
// Kernel 3: rmsnorm + modulate (output pre-rounded to tf32: GEMM-A input)
// ---------------------------------------------------------------------------
__global__ void __launch_bounds__(256) norm_mod(
    const float* __restrict__ x, const float* __restrict__ scale,
    const float* __restrict__ ada, int shOff, int scOff,
    float* __restrict__ y)
{
    const int row = blockIdx.x;
    const int b   = row >> 12;
    const float4 v = ((const float4*)(x + (size_t)row * 1024))[threadIdx.x];

    float ss = v.x * v.x + v.y * v.y + v.z * v.z + v.w * v.w;
    #pragma unroll
    for (int o = 16; o > 0; o >>= 1) ss += __shfl_xor_sync(0xffffffffu, ss, o);
    __shared__ float ws[8];
    if ((threadIdx.x & 31) == 0) ws[threadIdx.x >> 5] = ss;
    __syncthreads();
    float tot = 0.f;
    #pragma unroll
    for (int i = 0; i < 8; i++) tot += ws[i];
    const float r = rsqrtf(tot * (1.f / 1024.f) + 1e-5f);

    const int c = threadIdx.x * 4;
    const float* ab = ada + b * 6144;
    const float4 s   = *(const float4*)(scale + c);
    const float4 sh  = *(const float4*)(ab + shOff + c);
    const float4 scm = *(const float4*)(ab + scOff + c);
    float4 o;
    o.x = ftf(v.x * r * s.x * (1.f + scm.x) + sh.x);
    o.y = ftf(v.y * r * s.y * (1.f + scm.y) + sh.y);
    o.z = ftf(v.z * r * s.z * (1.f + scm.z) + sh.z);
    o.w = ftf(v.w * r * s.w * (1.f + scm.w) + sh.w);
    ((float4*)(y + (size_t)row * 1024))[threadIdx.x] = o;
}

// ---------------------------------------------------------------------------
// Kernel 4: tf32 tensor GEMM, C[M,N] = A[M,K] @ Bt[N,K]^T  (+epilogue)
//   CTA 256x128, BK=32, 256 threads = 8 warps (4 row-groups x 2 col-groups),
//   warp tile 64x64. A/Bt already tf32-rounded; Bt is N-major (k contiguous).
//   smem stride 40 floats; fragment loads are conflict-free float2 via the
//   logical-k permutation (q<4 -> k=2q, q>=4 -> k=2(q-4)+1 within each 8-blk).
//   MODE 0: store. 1: tf32(gelu). 2: res + gate*C.
// ---------------------------------------------------------------------------
#define GEMM_SMEM (4 * 30720)   // (2*256*40 + 2*128*40) floats

template <int MODE>
__global__ void __launch_bounds__(256, 1) gemm_tc(
    const float* __restrict__ A, const float* __restrict__ Bt,
    const float* __restrict__ bias, float* __restrict__ C,
    int N, int K,
    const float* __restrict__ res, const float* __restrict__ gate)
{
    extern __shared__ float sm[];
    float* As = sm;            // [2][256][40]
    float* Bs = sm + 20480;    // [2][128][40]
    const uint32_t as_u = smem_u32(As);
    const uint32_t bs_u = smem_u32(Bs);

    const int tid  = threadIdx.x;
    const int lane = tid & 31;
    const int warp = tid >> 5;
    const int g    = lane >> 2, tig = lane & 3;
    const int wm   = warp & 3;     // 0..3 -> 64-row group
    const int wn   = warp >> 2;    // 0..1 -> 64-col group
    const int cm   = blockIdx.y << 8;
    const int cn   = blockIdx.x << 7;
    const int KT   = K >> 5;

    // staging thread mapping
    const int a_r = tid >> 3, a_kc = (tid & 7) << 2;   // +32 rows per iter
    // (same pattern reused for B with 128 rows)

    auto fill = [&](int kt, int buf) {
        const int k0 = kt << 5;
        const float* Ag = A  + (size_t)(cm + a_r) * K + k0 + a_kc;
        uint32_t ad = as_u + ((buf * 10240 + a_r * 40 + a_kc) << 2);
        #pragma unroll
        for (int i = 0; i < 8; i++)
            cp16(ad + i * (32 * 40 * 4), Ag + (size_t)i * 32 * K);
        const float* Bg = Bt + (size_t)(cn + a_r) * K + k0 + a_kc;
        uint32_t bd = bs_u + ((buf * 5120 + a_r * 40 + a_kc) << 2);
        #pragma unroll
        for (int i = 0; i < 4; i++)
            cp16(bd + i * (32 * 40 * 4), Bg + (size_t)i * 32 * K);
    };

    float acc[4][8][4];
    #pragma unroll
    for (int mt = 0; mt < 4; mt++)
        #pragma unroll
        for (int nt = 0; nt < 8; nt++)
            #pragma unroll
            for (int i = 0; i < 4; i++) acc[mt][nt][i] = 0.f;

    fill(0, 0); CP_COMMIT();

    for (int kt = 0; kt < KT; kt++) {
        const int buf = kt & 1;
        if (kt + 1 < KT) { fill(kt + 1, buf ^ 1); CP_COMMIT(); CP_WAIT1(); }
        else             { CP_WAIT0(); }
        __syncthreads();

        const float* Ab = As + buf * 10240 + (wm * 64) * 40;
        const float* Bb = Bs + buf * 5120  + (wn * 64) * 40;
        #pragma unroll
        for (int ks = 0; ks < 4; ks++) {
            const int kcol = (ks << 3) + (tig << 1);
            float2 aa[4][2];
            #pragma unroll
            for (int mt = 0; mt < 4; mt++) {
                aa[mt][0] = *(const float2*)(Ab + (mt * 16 + g)     * 40 + kcol);
                aa[mt][1] = *(const float2*)(Ab + (mt * 16 + g + 8) * 40 + kcol);
            }
            #pragma unroll
            for (int nt = 0; nt < 8; nt++) {
                const float2 bb = *(const float2*)(Bb + (nt * 8 + g) * 40 + kcol);
                uint32_t b2[2] = { __float_as_uint(bb.x), __float_as_uint(bb.y) };
                #pragma unroll
                for (int mt = 0; mt < 4; mt++) {
                    uint32_t a4[4] = { __float_as_uint(aa[mt][0].x), __float_as_uint(aa[mt][1].x),
                                       __float_as_uint(aa[mt][0].y), __float_as_uint(aa[mt][1].y) };
                    mma8(acc[mt][nt], a4, b2);
                }
            }
        }
        __syncthreads();
    }

    // epilogue
    const int bb_i = cm >> 12;
    #pragma unroll
    for (int mt = 0; mt < 4; mt++) {
        const int row0 = cm + wm * 64 + mt * 16 + g;
        float* C0 = C + (size_t)row0 * N;
        float* C1 = C + (size_t)(row0 + 8) * N;
        const float* R0 = res + (size_t)row0 * N;
        const float* R1 = res + (size_t)(row0 + 8) * N;
        #pragma unroll
        for (int nt = 0; nt < 8; nt++) {
            const int col = cn + wn * 64 + nt * 8 + (tig << 1);
            const float bi0 = bias[col], bi1 = bias[col + 1];
            float v0 = acc[mt][nt][0] + bi0;
            float v1 = acc[mt][nt][1] + bi1;
            float v2 = acc[mt][nt][2] + bi0;
            float v3 = acc[mt][nt][3] + bi1;
            if (MODE == 1) {
                v0 = ftf(gelu_tanh(v0)); v1 = ftf(gelu_tanh(v1));
                v2 = ftf(gelu_tanh(v2)); v3 = ftf(gelu_tanh(v3));
            }
            if (MODE == 2) {
                const float g0 = gate[bb_i * 6144 + col];
                const float g1 = gate[bb_i * 6144 + col + 1];
                v0 = R0[col] + g0 * v0;  v1 = R0[col + 1] + g1 * v1;
                v2 = R1[col] + g0 * v2;  v3 = R1[col + 1] + g1 * v3;
            }
            *(float2*)(C0 + col) = make_float2(v0, v1);
            *(float2*)(C1 + col) = make_float2(v2, v3);
        }
    }
}

// ---------------------------------------------------------------------------
// Kernel 5: windowed attention (unchanged from R1 except tf32-rounded output)
// ---------------------------------------------------------------------------
#define ATTN_SMEM_BYTES (2 * 128 * 132 * 4)

__global__ void __launch_bounds__(256) attn_kernel(
    const float* __restrict__ qkv, float* __restrict__ obuf,
    const float2* __restrict__ rope)
{
    extern __shared__ float smn[];
    float* Qs = smn;
    float* Ks = smn + 128 * 132;

    const int tid  = threadIdx.x;
    const int lane = tid & 31, warp = tid >> 5;
    const int g    = lane >> 2, tig = lane & 3;
    const int h    = blockIdx.x & 7;
    const int w    = blockIdx.x >> 3;
    const size_t rowbase = (size_t)w * 128;

    for (int idx = tid; idx < 16384; idx += 256) {
        const int i = idx >> 7, d = idx & 127;
        const float* base = qkv + (rowbase + i) * 3072 + h * 128;
        const float2 sc = rope[i * 64 + (d >> 1)];
        const float q  = base[d];
        const float qr = (d < 64) ? -base[d + 64] : base[d - 64];
        Qs[i * 132 + d] = ftf(q * sc.y + qr * sc.x);
        const float* kb = base + 1024;
        const float kk  = kb[d];
        const float kr  = (d < 64) ? -kb[d + 64] : kb[d - 64];
        Ks[i * 132 + d] = ftf(kk * sc.y + kr * sc.x);
    }
    __syncthreads();

    float acc[16][4];
    #pragma unroll
    for (int nt = 0; nt < 16; nt++)
        #pragma unroll
        for (int i = 0; i < 4; i++) acc[nt][i] = 0.f;

    const int m0 = warp * 16 + g;
    #pragma unroll
    for (int ks = 0; ks < 16; ks++) {
        const int k0 = ks * 8 + tig;
        uint32_t a[4];
        a[0] = __float_as_uint(Qs[m0 * 132 + k0]);
        a[1] = __float_as_uint(Qs[(m0 + 8) * 132 + k0]);
        a[2] = __float_as_uint(Qs[m0 * 132 + k0 + 4]);
        a[3] = __float_as_uint(Qs[(m0 + 8) * 132 + k0 + 4]);
        #pragma unroll
        for (int nt = 0; nt < 16; nt++) {
            const int n = nt * 8 + g;
            uint32_t b[2];
            b[0] = __float_as_uint(Ks[n * 132 + k0]);
            b[1] = __float_as_uint(Ks[n * 132 + k0 + 4]);
            mma8(acc[nt], a, b);
        }
    }

    const float scl = 0.08838834764831845f;
    float mx0 = -1e30f, mx1 = -1e30f;
    #pragma unroll
    for (int nt = 0; nt < 16; nt++) {
        acc[nt][0] *= scl; acc[nt][1] *= scl; acc[nt][2] *= scl; acc[nt][3] *= scl;
        mx0 = fmaxf(mx0, fmaxf(acc[nt][0], acc[nt][1]));
        mx1 = fmaxf(mx1, fmaxf(acc[nt][2], acc[nt][3]));
    }
    mx0 = fmaxf(mx0, __shfl_xor_sync(0xffffffffu, mx0, 1));
    mx0 = fmaxf(mx0, __shfl_xor_sync(0xffffffffu, mx0, 2));
    mx1 = fmaxf(mx1, __shfl_xor_sync(0xffffffffu, mx1, 1));
    mx1 = fmaxf(mx1, __shfl_xor_sync(0xffffffffu, mx1, 2));

    float s0 = 0.f, s1 = 0.f;
    #pragma unroll
    for (int nt = 0; nt < 16; nt++) {
        acc[nt][0] = __expf(acc[nt][0] - mx0);
        acc[nt][1] = __expf(acc[nt][1] - mx0);
        acc[nt][2] = __expf(acc[nt][2] - mx1);
        acc[nt][3] = __expf(acc[nt][3] - mx1);
        s0 += acc[nt][0] + acc[nt][1];
        s1 += acc[nt][2] + acc[nt][3];
    }
    s0 += __shfl_xor_sync(0xffffffffu, s0, 1);
    s0 += __shfl_xor_sync(0xffffffffu, s0, 2);
    s1 += __shfl_xor_sync(0xffffffffu, s1, 1);
    s1 += __shfl_xor_sync(0xffffffffu, s1, 2);
    const float i0 = 1.f / s0, i1 = 1.f / s1;

    #pragma unroll
    for (int nt = 0; nt < 16; nt++) {
        const int c = nt * 8 + 2 * tig;
        Qs[m0 * 132 + c]           = ftf(acc[nt][0] * i0);
        Qs[m0 * 132 + c + 1]       = ftf(acc[nt][1] * i0);
        Qs[(m0 + 8) * 132 + c]     = ftf(acc[nt][2] * i1);
        Qs[(m0 + 8) * 132 + c + 1] = ftf(acc[nt][3] * i1);
    }
    __syncthreads();

    for (int idx = tid; idx < 16384; idx += 256) {
        const int j = idx >> 7, d = idx & 127;
        Ks[d * 132 + j] = ftf(qkv[(rowbase + j) * 3072 + 2048 + h * 128 + d]);
    }
    __syncthreads();

    #pragma unroll
    for (int nt = 0; nt < 16; nt++)
        #pragma unroll
        for (int i = 0; i < 4; i++) acc[nt][i] = 0.f;

    #pragma unroll
    for (int ks = 0; ks < 16; ks++) {
        const int k0 = ks * 8 + tig;
        uint32_t a[4];
        a[0] = __float_as_uint(Qs[m0 * 132 + k0]);
        a[1] = __float_as_uint(Qs[(m0 + 8) * 132 + k0]);
        a[2] = __float_as_uint(Qs[m0 * 132 + k0 + 4]);
        a[3] = __float_as_uint(Qs[(m0 + 8) * 132 + k0 + 4]);
        #pragma unroll
        for (int nt = 0; nt < 16; nt++) {
            const int n = nt * 8 + g;
            uint32_t b[2];
            b[0] = __float_as_uint(Ks[n * 132 + k0]);
            b[1] = __float_as_uint(Ks[n * 132 + k0 + 4]);
            mma8(acc[nt], a, b);
        }
    }

    // output is the A operand of the next GEMM -> pre-round to tf32
    #pragma unroll
    for (int nt = 0; nt < 16; nt++) {
        const int col = h * 128 + nt * 8 + 2 * tig;
        *(float2*)(obuf + (rowbase + m0) * 1024 + col) =
            make_float2(ftf(acc[nt][0]), ftf(acc[nt][1]));
        *(float2*)(obuf + (rowbase + m0 + 8) * 1024 + col) =
            make_float2(ftf(acc[nt][2]), ftf(acc[nt][3]));
    }
}

// ---------------------------------------------------------------------------
// host launcher
// ---------------------------------------------------------------------------
extern "C" void kernel_launch(void* const* d_in, const int* in_sizes, int n_in,
                              void* d_out, int out_size)
{
    const float* group_x = (const float*)d_in[0];
    const float* context = (const float*)d_in[1];
    const float* W_ada   = (const float*)d_in[2];
    const float* b_ada   = (const float*)d_in[3];
    const float* scale1  = (const float*)d_in[4];
    const float* W_qkv   = (const float*)d_in[5];
    const float* b_qkv   = (const float*)d_in[6];
    const float* W_out   = (const float*)d_in[7];
    const float* b_out   = (const float*)d_in[8];
    const float* scale2  = (const float*)d_in[9];
    const float* W_ff1   = (const float*)d_in[10];
    const float* b_ff1   = (const float*)d_in[11];
    const float* W_ff2   = (const float*)d_in[12];
    const float* b_ff2   = (const float*)d_in[13];
    float* out = (float*)d_out;

    float *ada, *x1, *qkv, *obuf, *res2, *hbuf, *h1;
    float *wqkv, *wout, *wff1, *wff2;
    float2* rope;
    cudaGetSymbolAddress((void**)&ada,  g_ada);
    cudaGetSymbolAddress((void**)&x1,   g_x1);
    cudaGetSymbolAddress((void**)&qkv,  g_qkv);
    cudaGetSymbolAddress((void**)&obuf, g_o);
    cudaGetSymbolAddress((void**)&res2, g_res);
    cudaGetSymbolAddress((void**)&hbuf, g_h);
    cudaGetSymbolAddress((void**)&h1,   g_h1);
    cudaGetSymbolAddress((void**)&rope, g_rope);
    cudaGetSymbolAddress((void**)&wqkv, g_wqkv);
    cudaGetSymbolAddress((void**)&wout, g_wout);
    cudaGetSymbolAddress((void**)&wff1, g_wff1);
    cudaGetSymbolAddress((void**)&wff2, g_wff2);

    cudaFuncSetAttribute(gemm_tc<0>, cudaFuncAttributeMaxDynamicSharedMemorySize, GEMM_SMEM);
    cudaFuncSetAttribute(gemm_tc<1>, cudaFuncAttributeMaxDynamicSharedMemorySize, GEMM_SMEM);
    cudaFuncSetAttribute(gemm_tc<2>, cudaFuncAttributeMaxDynamicSharedMemorySize, GEMM_SMEM);
    cudaFuncSetAttribute(attn_kernel, cudaFuncAttributeMaxDynamicSharedMemorySize, ATTN_SMEM_BYTES);

    const dim3 tb(32, 8);
    // weight prep (independent; graph can run them concurrently)
    transpose_round<<<dim3(3072 / 32, 1024 / 32), tb>>>(W_qkv, wqkv, 1024, 3072);
    transpose_round<<<dim3(1024 / 32, 1024 / 32), tb>>>(W_out, wout, 1024, 1024);
    transpose_round<<<dim3(4096 / 32, 1024 / 32), tb>>>(W_ff1, wff1, 1024, 4096);
    transpose_round<<<dim3(1024 / 32, 4096 / 32), tb>>>(W_ff2, wff2, 4096, 1024);

    ada_kernel<<<24, 256>>>(context, W_ada, b_ada, ada);
    rope_kernel<<<32, 256>>>(rope);
    norm_mod<<<32768, 256>>>(group_x, scale1, ada, 0, 1024, x1);

    // qkv = x1 @ W_qkv + b_qkv                     (M=32768, N=3072, K=1024)
    gemm_tc<0><<<dim3(24, 128), 256, GEMM_SMEM>>>(x1, wqkv, b_qkv, qkv,
                                                  3072, 1024, nullptr, nullptr);
    attn_kernel<<<2048, 256, ATTN_SMEM_BYTES>>>(qkv, obuf, rope);

    // res2 = group_x + g_msa * (obuf @ W_out + b_out)   (N=1024, K=1024)
    gemm_tc<2><<<dim3(8, 128), 256, GEMM_SMEM>>>(obuf, wout, b_out, res2,
                                                 1024, 1024, group_x, ada + 2048);
    norm_mod<<<32768, 256>>>(res2, scale2, ada, 3072, 4096, hbuf);

    // h1 = tf32(gelu(hbuf @ W_ff1 + b_ff1))        (N=4096, K=1024)
    gemm_tc<1><<<dim3(32, 128), 256, GEMM_SMEM>>>(hbuf, wff1, b_ff1, h1,
                                                  4096, 1024, nullptr, nullptr);
    // out = res2 + g_mlp * (h1 @ W_ff2 + b_ff2)    (N=1024, K=4096)
    gemm_tc<2><<<dim3(8, 128), 256, GEMM_SMEM>>>(h1, wff2, b_ff2, out,
                                                 1024, 4096, res2, ada + 5120);
}

// round 4
// speedup vs baseline: 1.6885x; 1.6631x over previous
#include <cuda_runtime.h>
#include <cuda_fp16.h>
#include <cstdint>

// ---------------------------------------------------------------------------
// B=8, L=4096, D=1024, H=8, DH=128, WIN=128; M = 32768.
// GEMMs: legacy mma.sync m16n8k16 fp16 (fp32 accum). fp16 mantissa (10b) ==
// tf32 mantissa, so accuracy matches the passing tf32 runs. All GEMM inputs
// are produced pre-converted to fp16 in a k-permuted layout so fragments are
// single conflict-free LDS.64 and staging is pure cp.async (no cvt).
// Permutation (within each 16-half k-block, at half2 granularity):
//   logical half2 j  ->  physical half2 (j<4 ? 2j : 2(j-4)+1)
// Applied to BOTH A and B k-dims => dot products invariant.
// ---------------------------------------------------------------------------

__device__ float  g_ada [8 * 6144];
__device__ __half g_x1  [33554432];    // norm1 output (fp16, permuted)
__device__ float  g_qkv [100663296];   // qkv (fp32: attention input)
__device__ __half g_o   [33554432];    // attention out (fp16, permuted)
__device__ float  g_res [33554432];    // residual after MSA (fp32)
__device__ __half g_h   [33554432];    // norm2 output (fp16, permuted)
__device__ __half g_h1  [134217728];   // ff hidden (fp16, permuted)
__device__ float2 g_rope[8192];
// transposed + fp16 weights (N-major, k contiguous & permuted)
__device__ __half g_wqkv[3145728];
__device__ __half g_wout[1048576];
__device__ __half g_wff1[4194304];
__device__ __half g_wff2[4194304];

// ---------------------------------------------------------------------------
// helpers
// ---------------------------------------------------------------------------
__device__ __forceinline__ float ftf(float x) {
    uint32_t u;
    asm("cvt.rna.tf32.f32 %0, %1;" : "=r"(u) : "f"(x));
    return __uint_as_float(u);
}

__device__ __forceinline__ float gelu_tanh(float x) {
    float u = 0.7978845608028654f * (x + 0.044715f * x * x * x);
    return 0.5f * x * (1.f + tanhf(u));
}

__device__ __forceinline__ uint32_t smem_u32(const void* p) {
    uint32_t a;
    asm("{ .reg .u64 t; cvta.to.shared.u64 t, %1; cvt.u32.u64 %0, t; }" : "=r"(a) : "l"(p));
    return a;
}

// start half-index of the permuted position for an EVEN column pair (col,col+1)
__device__ __forceinline__ int permc(int col) {
    int j  = (col & 15) >> 1;
    int p2 = (j < 4) ? (2 * j) : (2 * (j - 4) + 1);
    return (col & ~15) + 2 * p2;
}
// permuted half-index for a single half
__device__ __forceinline__ int permh(int k) {
    int j  = (k & 15) >> 1;
    int p2 = (j < 4) ? (2 * j) : (2 * (j - 4) + 1);
    return (k & ~15) + 2 * p2 + (k & 1);
}

// fp16 mma m16n8k16, fp32 accumulate
__device__ __forceinline__ void mma16(float* d, uint32_t a0, uint32_t a1,
                                      uint32_t a2, uint32_t a3,
                                      uint32_t b0, uint32_t b1) {
    asm volatile(
        "mma.sync.aligned.m16n8k16.row.col.f32.f16.f16.f32 "
        "{%0,%1,%2,%3}, {%4,%5,%6,%7}, {%8,%9}, {%0,%1,%2,%3};"
        : "+f"(d[0]), "+f"(d[1]), "+f"(d[2]), "+f"(d[3])
        : "r"(a0), "r"(a1), "r"(a2), "r"(a3), "r"(b0), "r"(b1));
}

// legacy tf32 mma for attention
__device__ __forceinline__ void mma8(float* d, const uint32_t* a, const uint32_t* b) {
    asm volatile(
        "mma.sync.aligned.m16n8k8.row.col.f32.tf32.tf32.f32 "
        "{%0,%1,%2,%3}, {%4,%5,%6,%7}, {%8,%9}, {%0,%1,%2,%3};"
        : "+f"(d[0]), "+f"(d[1]), "+f"(d[2]), "+f"(d[3])
        : "r"(a[0]), "r"(a[1]), "r"(a[2]), "r"(a[3]), "r"(b[0]), "r"(b[1]));
}

__device__ __forceinline__ void cp16(uint32_t dst, const void* src) {
    asm volatile("cp.async.cg.shared.global [%0], [%1], 16;" :: "r"(dst), "l"(src));
}
#define CP_COMMIT() asm volatile("cp.async.commit_group;" ::: "memory")
#define CP_WAIT1()  asm volatile("cp.async.wait_group 1;"  ::: "memory")
#define CP_WAIT0()  asm volatile("cp.async.wait_group 0;"  ::: "memory")

// ---------------------------------------------------------------------------
// Kernel 0: Wt[n][perm(k)] = fp16(W[k][n])
// ---------------------------------------------------------------------------
__global__ void __launch_bounds__(256) transpose_round(
    const float* __restrict__ W, __half* __restrict__ Wt, int K, int N)
{
    __shared__ float t[32][33];
    const int kb = blockIdx.y * 32, nb = blockIdx.x * 32;
    const int tx = threadIdx.x, ty = threadIdx.y;   // 32 x 8
    #pragma unroll
    for (int i = 0; i < 4; i++)
        t[ty + 8 * i][tx] = W[(size_t)(kb + ty + 8 * i) * N + nb + tx];
    __syncthreads();
    #pragma unroll
    for (int i = 0; i < 4; i++)
        Wt[(size_t)(nb + ty + 8 * i) * K + kb + permh(tx)] =
            __float2half_rn(t[tx][ty + 8 * i]);
}

// ---------------------------------------------------------------------------
// Kernel 1: ada = silu(context) @ W_ada + b_ada
// ---------------------------------------------------------------------------
__global__ void __launch_bounds__(256) ada_kernel(
    const float* __restrict__ ctx, const float* __restrict__ W,
    const float* __restrict__ bias, float* __restrict__ ada)
{
    __shared__ float sctx[8 * 1024];
    for (int i = threadIdx.x; i < 8192; i += 256) {
        float c = ctx[i];
        sctx[i] = c / (1.f + __expf(-c));
    }
    __syncthreads();
    const int col = blockIdx.x * 256 + threadIdx.x;
    float acc[8] = {0, 0, 0, 0, 0, 0, 0, 0};
    for (int k = 0; k < 1024; k++) {
        float w = W[(size_t)k * 6144 + col];
        #pragma unroll
        for (int b = 0; b < 8; b++) acc[b] += sctx[b * 1024 + k] * w;
    }
    float bv = bias[col];
    #pragma unroll
    for (int b = 0; b < 8; b++) ada[b * 6144 + col] = acc[b] + bv;
}

// ---------------------------------------------------------------------------
// Kernel 2: rope table
// ---------------------------------------------------------------------------
__global__ void rope_kernel(float2* __restrict__ tab)
{
    int idx = blockIdx.x * 256 + threadIdx.x;
    if (idx < 8192) {
        int pos = idx >> 6;
        int i   = idx & 63;
        float freq = powf(10000.f, -(float)(2 * i) / 128.f);
        float ang  = (float)pos * freq;
        tab[idx] = make_float2(sinf(ang), cosf(ang));
    }
}

// ---------------------------------------------------------------------------
// Kernel 3: rmsnorm + modulate -> fp16 permuted
// ---------------------------------------------------------------------------
__global__ void __launch_bounds__(256) norm_mod(
    const float* __restrict__ x, const float* __restrict__ scale,
    const float* __restrict__ ada, int shOff, int scOff,
    __half* __restrict__ y)
{
    const int row = blockIdx.x;
    const int b   = row >> 12;
    const float4 v = ((const float4*)(x + (size_t)row * 1024))[threadIdx.x];

    float ss = v.x * v.x + v.y * v.y + v.z * v.z + v.w * v.w;
    #pragma unroll
    for (int o = 16; o > 0; o >>= 1) ss += __shfl_xor_sync(0xffffffffu, ss, o);
    __shared__ float ws[8];
    if ((threadIdx.x & 31) == 0) ws[threadIdx.x >> 5] = ss;
    __syncthreads();
    float tot = 0.f;
    #pragma unroll
    for (int i = 0; i < 8; i++) tot += ws[i];
    const float r = rsqrtf(tot * (1.f / 1024.f) + 1e-5f);

    const int c = threadIdx.x * 4;
    const float* ab = ada + b * 6144;
    const float4 s   = *(const float4*)(scale + c);
    const float4 sh  = *(const float4*)(ab + shOff + c);
    const float4 scm = *(const float4*)(ab + scOff + c);
    float o0 = v.x * r * s.x * (1.f + scm.x) + sh.x;
    float o1 = v.y * r * s.y * (1.f + scm.y) + sh.y;
    float o2 = v.z * r * s.z * (1.f + scm.z) + sh.z;
    float o3 = v.w * r * s.w * (1.f + scm.w) + sh.w;
    __half* yr = y + (size_t)row * 1024;
    *(half2*)(yr + permc(c))     = __floats2half2_rn(o0, o1);
    *(half2*)(yr + permc(c + 2)) = __floats2half2_rn(o2, o3);
}

// ---------------------------------------------------------------------------
// Kernel 4: fp16 tensor GEMM, C[M,N] = A[M,K] @ Bt[N,K]^T  (+epilogue)
//   CTA 256x128, BK=64, 256 threads = 8 warps (4x2), warp tile 64x64.
//   A/Bt fp16 permuted; smem row = 64 data halfs + 16 pad (stride 160B).
//   Fragments: one LDS.64 per (row-pair half, ks): conflict-free.
//   MODE 0: fp32 store. 1: fp16-permuted gelu store. 2: fp32 res + gate*C.
// ---------------------------------------------------------------------------
#define GEMM_SMEM 122880   // 2*256*160 + 2*128*160

template <int MODE>
__global__ void __launch_bounds__(256, 1) gemm_fp16(
    const __half* __restrict__ A, const __half* __restrict__ Bt,
    const float* __restrict__ bias,
    float* __restrict__ C, __half* __restrict__ Ch,
    int N, int K,
    const float* __restrict__ res, const float* __restrict__ gate)
{
    extern __shared__ char smem[];
    const uint32_t sm_u = smem_u32(smem);

    const int tid  = threadIdx.x;
    const int lane = tid & 31;
    const int warp = tid >> 5;
    const int g    = lane >> 2, tig = lane & 3;
    const int wm   = warp & 3;     // 64-row group
    const int wn   = warp >> 2;    // 64-col group
    const int cm   = blockIdx.y << 8;
    const int cn   = blockIdx.x << 7;
    const int KT   = K >> 6;

    // staging: chunk = 16B = 8 halfs; A: 2048 chunks, B: 1024 chunks
    auto fill = [&](int kt, int buf) {
        const int k0 = kt << 6;
        #pragma unroll
        for (int i = 0; i < 8; i++) {
            const int c = tid + (i << 8);
            const int row = c >> 3, pos = c & 7;
            cp16(sm_u + buf * 40960 + row * 160 + pos * 16,
                 A + (size_t)(cm + row) * K + k0 + pos * 8);
        }
        #pragma unroll
        for (int i = 0; i < 4; i++) {
            const int c = tid + (i << 8);
            const int row = c >> 3, pos = c & 7;
            cp16(sm_u + 81920 + buf * 20480 + row * 160 + pos * 16,
                 Bt + (size_t)(cn + row) * K + k0 + pos * 8);
        }
    };

    float acc[4][8][4];
    #pragma unroll
    for (int mt = 0; mt < 4; mt++)
        #pragma unroll
        for (int nt = 0; nt < 8; nt++)
            #pragma unroll
            for (int i = 0; i < 4; i++) acc[mt][nt][i] = 0.f;

    fill(0, 0); CP_COMMIT();

    for (int kt = 0; kt < KT; kt++) {
        const int buf = kt & 1;
        if (kt + 1 < KT) { fill(kt + 1, buf ^ 1); CP_COMMIT(); CP_WAIT1(); }
        else             { CP_WAIT0(); }
        __syncthreads();

        const __half* Ab = (const __half*)(smem + buf * 40960) + (wm * 64) * 80;
        const __half* Bb = (const __half*)(smem + 81920 + buf * 20480) + (wn * 64) * 80;
        #pragma unroll
        for (int ks = 0; ks < 4; ks++) {
            const int koff = ks * 16 + tig * 4;
            uint2 a_lo[4], a_hi[4];
            #pragma unroll
            for (int mt = 0; mt < 4; mt++) {
                a_lo[mt] = *(const uint2*)(Ab + (mt * 16 + g)     * 80 + koff);
                a_hi[mt] = *(const uint2*)(Ab + (mt * 16 + g + 8) * 80 + koff);
            }
            #pragma unroll
            for (int nt = 0; nt < 8; nt++) {
                const uint2 b2 = *(const uint2*)(Bb + (nt * 8 + g) * 80 + koff);
                #pragma unroll
                for (int mt = 0; mt < 4; mt++)
                    mma16(acc[mt][nt], a_lo[mt].x, a_hi[mt].x,
                          a_lo[mt].y, a_hi[mt].y, b2.x, b2.y);
            }
        }
        __syncthreads();
    }

    // epilogue
    const int bb_i = cm >> 12;
    #pragma unroll
    for (int mt = 0; mt < 4; mt++) {
        const int row0 = cm + wm * 64 + mt * 16 + g;
        #pragma unroll
        for (int nt = 0; nt < 8; nt++) {
            const int col = cn + wn * 64 + nt * 8 + (tig << 1);
            const float bi0 = bias[col], bi1 = bias[col + 1];
            float v0 = acc[mt][nt][0] + bi0;
            float v1 = acc[mt][nt][1] + bi1;
            float v2 = acc[mt][nt][2] + bi0;
            float v3 = acc[mt][nt][3] + bi1;
            if (MODE == 1) {
                v0 = gelu_tanh(v0); v1 = gelu_tanh(v1);
                v2 = gelu_tanh(v2); v3 = gelu_tanh(v3);
                const int p = permc(col);
                *(half2*)(Ch + (size_t)row0 * N + p)       = __floats2half2_rn(v0, v1);
                *(half2*)(Ch + (size_t)(row0 + 8) * N + p) = __floats2half2_rn(v2, v3);
            } else {
                if (MODE == 2) {
                    const float g0 = gate[bb_i * 6144 + col];
                    const float g1 = gate[bb_i * 6144 + col + 1];
                    const float2 r0 = *(const float2*)(res + (size_t)row0 * N + col);
                    const float2 r1 = *(const float2*)(res + (size_t)(row0 + 8) * N + col);
                    v0 = r0.x + g0 * v0;  v1 = r0.y + g1 * v1;
                    v2 = r1.x + g0 * v2;  v3 = r1.y + g1 * v3;
                }
                *(float2*)(C + (size_t)row0 * N + col)       = make_float2(v0, v1);
                *(float2*)(C + (size_t)(row0 + 8) * N + col) = make_float2(v2, v3);
            }
        }
    }
}

// ---------------------------------------------------------------------------
// Kernel 5: windowed attention (tf32 mma; output fp16 permuted)
// ---------------------------------------------------------------------------
#define ATTN_SMEM_BYTES (2 * 128 * 132 * 4)

__global__ void __launch_bounds__(256) attn_kernel(
    const float* __restrict__ qkv, __half* __restrict__ obuf,
    const float2* __restrict__ rope)
{
    extern __shared__ float smn[];
    float* Qs = smn;
    float* Ks = smn + 128 * 132;

    const int tid  = threadIdx.x;
    const int lane = tid & 31, warp = tid >> 5;
    const int g    = lane >> 2, tig = lane & 3;
    const int h    = blockIdx.x & 7;
    const int w    = blockIdx.x >> 3;
    const size_t rowbase = (size_t)w * 128;

    for (int idx = tid; idx < 16384; idx += 256) {
        const int i = idx >> 7, d = idx & 127;
        const float* base = qkv + (rowbase + i) * 3072 + h * 128;
        const float2 sc = rope[i * 64 + (d >> 1)];
        const float q  = base[d];
        const float qr = (d < 64) ? -base[d + 64] : base[d - 64];
        Qs[i * 132 + d] = ftf(q * sc.y + qr * sc.x);
        const float* kb = base + 1024;
        const float kk  = kb[d];
        const float kr  = (d < 64) ? -kb[d + 64] : kb[d - 64];
        Ks[i * 132 + d] = ftf(kk * sc.y + kr * sc.x);
    }
    __syncthreads();

    float acc[16][4];
    #pragma unroll
    for (int nt = 0; nt < 16; nt++)
        #pragma unroll
        for (int i = 0; i < 4; i++) acc[nt][i] = 0.f;

    const int m0 = warp * 16 + g;
    #pragma unroll
    for (int ks = 0; ks < 16; ks++) {
        const int k0 = ks * 8 + tig;
        uint32_t a[4];
        a[0] = __float_as_uint(Qs[m0 * 132 + k0]);
        a[1] = __float_as_uint(Qs[(m0 + 8) * 132 + k0]);
        a[2] = __float_as_uint(Qs[m0 * 132 + k0 + 4]);
        a[3] = __float_as_uint(Qs[(m0 + 8) * 132 + k0 + 4]);
        #pragma unroll
        for (int nt = 0; nt < 16; nt++) {
            const int n = nt * 8 + g;
            uint32_t b[2];
            b[0] = __float_as_uint(Ks[n * 132 + k0]);
            b[1] = __float_as_uint(Ks[n * 132 + k0 + 4]);
            mma8(acc[nt], a, b);
        }
    }

    const float scl = 0.08838834764831845f;
    float mx0 = -1e30f, mx1 = -1e30f;
    #pragma unroll
    for (int nt = 0; nt < 16; nt++) {
        acc[nt][0] *= scl; acc[nt][1] *= scl; acc[nt][2] *= scl; acc[nt][3] *= scl;
        mx0 = fmaxf(mx0, fmaxf(acc[nt][0], acc[nt][1]));
        mx1 = fmaxf(mx1, fmaxf(acc[nt][2], acc[nt][3]));
    }
    mx0 = fmaxf(mx0, __shfl_xor_sync(0xffffffffu, mx0, 1));
    mx0 = fmaxf(mx0, __shfl_xor_sync(0xffffffffu, mx0, 2));
    mx1 = fmaxf(mx1, __shfl_xor_sync(0xffffffffu, mx1, 1));
    mx1 = fmaxf(mx1, __shfl_xor_sync(0xffffffffu, mx1, 2));

    float s0 = 0.f, s1 = 0.f;
    #pragma unroll
    for (int nt = 0; nt < 16; nt++) {
        acc[nt][0] = __expf(acc[nt][0] - mx0);
        acc[nt][1] = __expf(acc[nt][1] - mx0);
        acc[nt][2] = __expf(acc[nt][2] - mx1);
        acc[nt][3] = __expf(acc[nt][3] - mx1);
        s0 += acc[nt][0] + acc[nt][1];
        s1 += acc[nt][2] + acc[nt][3];
    }
    s0 += __shfl_xor_sync(0xffffffffu, s0, 1);
    s0 += __shfl_xor_sync(0xffffffffu, s0, 2);
    s1 += __shfl_xor_sync(0xffffffffu, s1, 1);
    s1 += __shfl_xor_sync(0xffffffffu, s1, 2);
    const float i0 = 1.f / s0, i1 = 1.f / s1;

    #pragma unroll
    for (int nt = 0; nt < 16; nt++) {
        const int c = nt * 8 + 2 * tig;
        Qs[m0 * 132 + c]           = ftf(acc[nt][0] * i0);
        Qs[m0 * 132 + c + 1]       = ftf(acc[nt][1] * i0);
        Qs[(m0 + 8) * 132 + c]     = ftf(acc[nt][2] * i1);
        Qs[(m0 + 8) * 132 + c + 1] = ftf(acc[nt][3] * i1);
    }
    __syncthreads();

    for (int idx = tid; idx < 16384; idx += 256) {
        const int j = idx >> 7, d = idx & 127;
        Ks[d * 132 + j] = ftf(qkv[(rowbase + j) * 3072 + 2048 + h * 128 + d]);
    }
    __syncthreads();

    #pragma unroll
    for (int nt = 0; nt < 16; nt++)
        #pragma unroll
        for (int i = 0; i < 4; i++) acc[nt][i] = 0.f;

    #pragma unroll
    for (int ks = 0; ks < 16; ks++) {
        const int k0 = ks * 8 + tig;
        uint32_t a[4];
        a[0] = __float_as_uint(Qs[m0 * 132 + k0]);
        a[1] = __float_as_uint(Qs[(m0 + 8) * 132 + k0]);
        a[2] = __float_as_uint(Qs[m0 * 132 + k0 + 4]);
        a[3] = __float_as_uint(Qs[(m0 + 8) * 132 + k0 + 4]);
        #pragma unroll
        for (int nt = 0; nt < 16; nt++) {
            const int n = nt * 8 + g;
            uint32_t b[2];
            b[0] = __float_as_uint(Ks[n * 132 + k0]);
            b[1] = __float_as_uint(Ks[n * 132 + k0 + 4]);
            mma8(acc[nt], a, b);
        }
    }

    // fp16 permuted output (next GEMM's A operand)
    #pragma unroll
    for (int nt = 0; nt < 16; nt++) {
        const int col = h * 128 + nt * 8 + 2 * tig;
        const int p = permc(col);
        *(half2*)(obuf + (rowbase + m0) * 1024 + p) =
            __floats2half2_rn(acc[nt][0], acc[nt][1]);
        *(half2*)(obuf + (rowbase + m0 + 8) * 1024 + p) =
            __floats2half2_rn(acc[nt][2], acc[nt][3]);
    }
}

// ---------------------------------------------------------------------------
// host launcher
// ---------------------------------------------------------------------------
extern "C" void kernel_launch(void* const* d_in, const int* in_sizes, int n_in,
                              void* d_out, int out_size)
{
    const float* group_x = (const float*)d_in[0];
    const float* context = (const float*)d_in[1];
    const float* W_ada   = (const float*)d_in[2];
    const float* b_ada   = (const float*)d_in[3];
    const float* scale1  = (const float*)d_in[4];
    const float* W_qkv   = (const float*)d_in[5];
    const float* b_qkv   = (const float*)d_in[6];
    const float* W_out   = (const float*)d_in[7];
    const float* b_out   = (const float*)d_in[8];
    const float* scale2  = (const float*)d_in[9];
    const float* W_ff1   = (const float*)d_in[10];
    const float* b_ff1   = (const float*)d_in[11];
    const float* W_ff2   = (const float*)d_in[12];
    const float* b_ff2   = (const float*)d_in[13];
    float* out = (float*)d_out;

    float *ada, *qkv, *res2;
    __half *x1, *obuf, *hbuf, *h1, *wqkv, *wout, *wff1, *wff2;
    float2* rope;
    cudaGetSymbolAddress((void**)&ada,  g_ada);
    cudaGetSymbolAddress((void**)&x1,   g_x1);
    cudaGetSymbolAddress((void**)&qkv,  g_qkv);
    cudaGetSymbolAddress((void**)&obuf, g_o);
    cudaGetSymbolAddress((void**)&res2, g_res);
    cudaGetSymbolAddress((void**)&hbuf, g_h);
    cudaGetSymbolAddress((void**)&h1,   g_h1);
    cudaGetSymbolAddress((void**)&rope, g_rope);
    cudaGetSymbolAddress((void**)&wqkv, g_wqkv);
    cudaGetSymbolAddress((void**)&wout, g_wout);
    cudaGetSymbolAddress((void**)&wff1, g_wff1);
    cudaGetSymbolAddress((void**)&wff2, g_wff2);

    cudaFuncSetAttribute(gemm_fp16<0>, cudaFuncAttributeMaxDynamicSharedMemorySize, GEMM_SMEM);
    cudaFuncSetAttribute(gemm_fp16<1>, cudaFuncAttributeMaxDynamicSharedMemorySize, GEMM_SMEM);
    cudaFuncSetAttribute(gemm_fp16<2>, cudaFuncAttributeMaxDynamicSharedMemorySize, GEMM_SMEM);
    cudaFuncSetAttribute(attn_kernel,  cudaFuncAttributeMaxDynamicSharedMemorySize, ATTN_SMEM_BYTES);

    const dim3 tb(32, 8);
    transpose_round<<<dim3(3072 / 32, 1024 / 32), tb>>>(W_qkv, wqkv, 1024, 3072);
    transpose_round<<<dim3(1024 / 32, 1024 / 32), tb>>>(W_out, wout, 1024, 1024);
    transpose_round<<<dim3(4096 / 32, 1024 / 32), tb>>>(W_ff1, wff1, 1024, 4096);
    transpose_round<<<dim3(1024 / 32, 4096 / 32), tb>>>(W_ff2, wff2, 4096, 1024);

    ada_kernel<<<24, 256>>>(context, W_ada, b_ada, ada);
    rope_kernel<<<32, 256>>>(rope);
    norm_mod<<<32768, 256>>>(group_x, scale1, ada, 0, 1024, x1);

    // qkv = x1 @ W_qkv + b_qkv                   (N=3072, K=1024) -> fp32
    gemm_fp16<0><<<dim3(24, 128), 256, GEMM_SMEM>>>(x1, wqkv, b_qkv, qkv, nullptr,
                                                    3072, 1024, nullptr, nullptr);
    attn_kernel<<<2048, 256, ATTN_SMEM_BYTES>>>(qkv, obuf, rope);

    // res2 = group_x + g_msa * (obuf @ W_out + b_out)   (N=1024, K=1024)
    gemm_fp16<2><<<dim3(8, 128), 256, GEMM_SMEM>>>(obuf, wout, b_out, res2, nullptr,
                                                   1024, 1024, group_x, ada + 2048);
    norm_mod<<<32768, 256>>>(res2, scale2, ada, 3072, 4096, hbuf);

    // h1 = gelu(hbuf @ W_ff1 + b_ff1)            (N=4096, K=1024) -> fp16 perm
    gemm_fp16<1><<<dim3(32, 128), 256, GEMM_SMEM>>>(hbuf, wff1, b_ff1, nullptr, h1,
                                                    4096, 1024, nullptr, nullptr);
    // out = res2 + g_mlp * (h1 @ W_ff2 + b_ff2)  (N=1024, K=4096)
    gemm_fp16<2><<<dim3(8, 128), 256, GEMM_SMEM>>>(h1, wff2, b_ff2, out, nullptr,
                                                   1024, 4096, res2, ada + 5120);
}

// round 6
// speedup vs baseline: 1.8824x; 1.1148x over previous
#include <cuda_runtime.h>
#include <cuda_fp16.h>
#include <cstdint>

// ---------------------------------------------------------------------------
// B=8, L=4096, D=1024, H=8, DH=128, WIN=128; M = 32768.
// GEMMs: legacy mma.sync m16n8k16 fp16 (fp32 accum), k-permuted operand layout.
// Attention: fp16 mma + ldmatrix, natural smem layouts, P kept in registers.
// ---------------------------------------------------------------------------

__device__ float  g_ada [8 * 6144];
__device__ __half g_x1  [33554432];    // norm1 output (fp16, permuted)
__device__ __half g_qkv [100663296];   // qkv (fp16, natural)
__device__ __half g_o   [33554432];    // attention out (fp16, permuted)
__device__ float  g_res [33554432];    // residual after MSA (fp32)
__device__ __half g_h   [33554432];    // norm2 output (fp16, permuted)
__device__ __half g_h1  [134217728];   // ff hidden (fp16, permuted)
__device__ float2 g_rope[8192];
__device__ __half g_wqkv[3145728];
__device__ __half g_wout[1048576];
__device__ __half g_wff1[4194304];
__device__ __half g_wff2[4194304];

// ---------------------------------------------------------------------------
// helpers
// ---------------------------------------------------------------------------
__device__ __forceinline__ float gelu_tanh(float x) {
    float u = 0.7978845608028654f * (x + 0.044715f * x * x * x);
    return 0.5f * x * (1.f + tanhf(u));
}

__device__ __forceinline__ uint32_t smem_u32(const void* p) {
    uint32_t a;
    asm("{ .reg .u64 t; cvta.to.shared.u64 t, %1; cvt.u32.u64 %0, t; }" : "=r"(a) : "l"(p));
    return a;
}

// bitcast half2 -> u32 (register)
__device__ __forceinline__ uint32_t h2u(half2 h) {
    uint32_t u;
    memcpy(&u, &h, 4);
    return u;
}

// permuted half-index helpers (GEMM operand layout)
__device__ __forceinline__ int permc(int col) {
    int j  = (col & 15) >> 1;
    int p2 = (j < 4) ? (2 * j) : (2 * (j - 4) + 1);
    return (col & ~15) + 2 * p2;
}
__device__ __forceinline__ int permh(int k) {
    int j  = (k & 15) >> 1;
    int p2 = (j < 4) ? (2 * j) : (2 * (j - 4) + 1);
    return (k & ~15) + 2 * p2 + (k & 1);
}

__device__ __forceinline__ void mma16(float* d, uint32_t a0, uint32_t a1,
                                      uint32_t a2, uint32_t a3,
                                      uint32_t b0, uint32_t b1) {
    asm volatile(
        "mma.sync.aligned.m16n8k16.row.col.f32.f16.f16.f32 "
        "{%0,%1,%2,%3}, {%4,%5,%6,%7}, {%8,%9}, {%0,%1,%2,%3};"
        : "+f"(d[0]), "+f"(d[1]), "+f"(d[2]), "+f"(d[3])
        : "r"(a0), "r"(a1), "r"(a2), "r"(a3), "r"(b0), "r"(b1));
}

__device__ __forceinline__ void ldsm_x4(uint32_t& r0, uint32_t& r1,
                                        uint32_t& r2, uint32_t& r3, uint32_t a) {
    asm volatile("ldmatrix.sync.aligned.m8n8.x4.shared.b16 {%0,%1,%2,%3}, [%4];"
                 : "=r"(r0), "=r"(r1), "=r"(r2), "=r"(r3) : "r"(a));
}
__device__ __forceinline__ void ldsm_x4t(uint32_t& r0, uint32_t& r1,
                                         uint32_t& r2, uint32_t& r3, uint32_t a) {
    asm volatile("ldmatrix.sync.aligned.m8n8.x4.trans.shared.b16 {%0,%1,%2,%3}, [%4];"
                 : "=r"(r0), "=r"(r1), "=r"(r2), "=r"(r3) : "r"(a));
}

__device__ __forceinline__ void cp16(uint32_t dst, const void* src) {
    asm volatile("cp.async.cg.shared.global [%0], [%1], 16;" :: "r"(dst), "l"(src));
}
#define CP_COMMIT() asm volatile("cp.async.commit_group;" ::: "memory")
#define CP_WAIT1()  asm volatile("cp.async.wait_group 1;"  ::: "memory")
#define CP_WAIT0()  asm volatile("cp.async.wait_group 0;"  ::: "memory")

// ---------------------------------------------------------------------------
// Kernel 0: Wt[n][perm(k)] = fp16(W[k][n])
// ---------------------------------------------------------------------------
__global__ void __launch_bounds__(256) transpose_round(
    const float* __restrict__ W, __half* __restrict__ Wt, int K, int N)
{
    __shared__ float t[32][33];
    const int kb = blockIdx.y * 32, nb = blockIdx.x * 32;
    const int tx = threadIdx.x, ty = threadIdx.y;   // 32 x 8
    #pragma unroll
    for (int i = 0; i < 4; i++)
        t[ty + 8 * i][tx] = W[(size_t)(kb + ty + 8 * i) * N + nb + tx];
    __syncthreads();
    #pragma unroll
    for (int i = 0; i < 4; i++)
        Wt[(size_t)(nb + ty + 8 * i) * K + kb + permh(tx)] =
            __float2half_rn(t[tx][ty + 8 * i]);
}

// ---------------------------------------------------------------------------
// Kernel 1: ada = silu(context) @ W_ada + b_ada
// ---------------------------------------------------------------------------
__global__ void __launch_bounds__(256) ada_kernel(
    const float* __restrict__ ctx, const float* __restrict__ W,
    const float* __restrict__ bias, float* __restrict__ ada)
{
    __shared__ float sctx[8 * 1024];
    for (int i = threadIdx.x; i < 8192; i += 256) {
        float c = ctx[i];
        sctx[i] = c / (1.f + __expf(-c));
    }
    __syncthreads();
    const int col = blockIdx.x * 256 + threadIdx.x;
    float acc[8] = {0, 0, 0, 0, 0, 0, 0, 0};
    for (int k = 0; k < 1024; k++) {
        float w = W[(size_t)k * 6144 + col];
        #pragma unroll
        for (int b = 0; b < 8; b++) acc[b] += sctx[b * 1024 + k] * w;
    }
    float bv = bias[col];
    #pragma unroll
    for (int b = 0; b < 8; b++) ada[b * 6144 + col] = acc[b] + bv;
}

// ---------------------------------------------------------------------------
// Kernel 2: rope table
// ---------------------------------------------------------------------------
__global__ void rope_kernel(float2* __restrict__ tab)
{
    int idx = blockIdx.x * 256 + threadIdx.x;
    if (idx < 8192) {
        int pos = idx >> 6;
        int i   = idx & 63;
        float freq = powf(10000.f, -(float)(2 * i) / 128.f);
        float ang  = (float)pos * freq;
        tab[idx] = make_float2(sinf(ang), cosf(ang));
    }
}

// ---------------------------------------------------------------------------
// Kernel 3: rmsnorm + modulate -> fp16 permuted
// ---------------------------------------------------------------------------
__global__ void __launch_bounds__(256) norm_mod(
    const float* __restrict__ x, const float* __restrict__ scale,
    const float* __restrict__ ada, int shOff, int scOff,
    __half* __restrict__ y)
{
    const int row = blockIdx.x;
    const int b   = row >> 12;
    const float4 v = ((const float4*)(x + (size_t)row * 1024))[threadIdx.x];

    float ss = v.x * v.x + v.y * v.y + v.z * v.z + v.w * v.w;
    #pragma unroll
    for (int o = 16; o > 0; o >>= 1) ss += __shfl_xor_sync(0xffffffffu, ss, o);
    __shared__ float ws[8];
    if ((threadIdx.x & 31) == 0) ws[threadIdx.x >> 5] = ss;
    __syncthreads();
    float tot = 0.f;
    #pragma unroll
    for (int i = 0; i < 8; i++) tot += ws[i];
    const float r = rsqrtf(tot * (1.f / 1024.f) + 1e-5f);

    const int c = threadIdx.x * 4;
    const float* ab = ada + b * 6144;
    const float4 s   = *(const float4*)(scale + c);
    const float4 sh  = *(const float4*)(ab + shOff + c);
    const float4 scm = *(const float4*)(ab + scOff + c);
    float o0 = v.x * r * s.x * (1.f + scm.x) + sh.x;
    float o1 = v.y * r * s.y * (1.f + scm.y) + sh.y;
    float o2 = v.z * r * s.z * (1.f + scm.z) + sh.z;
    float o3 = v.w * r * s.w * (1.f + scm.w) + sh.w;
    __half* yr = y + (size_t)row * 1024;
    *(half2*)(yr + permc(c))     = __floats2half2_rn(o0, o1);
    *(half2*)(yr + permc(c + 2)) = __floats2half2_rn(o2, o3);
}

// ---------------------------------------------------------------------------
// Kernel 4: fp16 tensor GEMM, C[M,N] = A[M,K] @ Bt[N,K]^T  (+epilogue)
//   MODE 0: fp32 store. 1: fp16-permuted gelu. 2: fp32 res+gate*C.
//   MODE 3: fp16 natural store (qkv for attention).
// ---------------------------------------------------------------------------
#define GEMM_SMEM 122880   // 2*256*160 + 2*128*160

template <int MODE>
__global__ void __launch_bounds__(256, 1) gemm_fp16(
    const __half* __restrict__ A, const __half* __restrict__ Bt,
    const float* __restrict__ bias,
    float* __restrict__ C, __half* __restrict__ Ch,
    int N, int K,
    const float* __restrict__ res, const float* __restrict__ gate)
{
    extern __shared__ char smem[];
    const uint32_t sm_u = smem_u32(smem);

    const int tid  = threadIdx.x;
    const int lane = tid & 31;
    const int warp = tid >> 5;
    const int g    = lane >> 2, tig = lane & 3;
    const int wm   = warp & 3;
    const int wn   = warp >> 2;
    const int cm   = blockIdx.y << 8;
    const int cn   = blockIdx.x << 7;
    const int KT   = K >> 6;

    auto fill = [&](int kt, int buf) {
        const int k0 = kt << 6;
        #pragma unroll
        for (int i = 0; i < 8; i++) {
            const int c = tid + (i << 8);
            const int row = c >> 3, pos = c & 7;
            cp16(sm_u + buf * 40960 + row * 160 + pos * 16,
                 A + (size_t)(cm + row) * K + k0 + pos * 8);
        }
        #pragma unroll
        for (int i = 0; i < 4; i++) {
            const int c = tid + (i << 8);
            const int row = c >> 3, pos = c & 7;
            cp16(sm_u + 81920 + buf * 20480 + row * 160 + pos * 16,
                 Bt + (size_t)(cn + row) * K + k0 + pos * 8);
        }
    };

    float acc[4][8][4];
    #pragma unroll
    for (int mt = 0; mt < 4; mt++)
        #pragma unroll
        for (int nt = 0; nt < 8; nt++)
            #pragma unroll
            for (int i = 0; i < 4; i++) acc[mt][nt][i] = 0.f;

    fill(0, 0); CP_COMMIT();

    for (int kt = 0; kt < KT; kt++) {
        const int buf = kt & 1;
        if (kt + 1 < KT) { fill(kt + 1, buf ^ 1); CP_COMMIT(); CP_WAIT1(); }
        else             { CP_WAIT0(); }
        __syncthreads();

        const __half* Ab = (const __half*)(smem + buf * 40960) + (wm * 64) * 80;
        const __half* Bb = (const __half*)(smem + 81920 + buf * 20480) + (wn * 64) * 80;
        #pragma unroll
        for (int ks = 0; ks < 4; ks++) {
            const int koff = ks * 16 + tig * 4;
            uint2 a_lo[4], a_hi[4];
            #pragma unroll
            for (int mt = 0; mt < 4; mt++) {
                a_lo[mt] = *(const uint2*)(Ab + (mt * 16 + g)     * 80 + koff);
                a_hi[mt] = *(const uint2*)(Ab + (mt * 16 + g + 8) * 80 + koff);
            }
            #pragma unroll
            for (int nt = 0; nt < 8; nt++) {
                const uint2 b2 = *(const uint2*)(Bb + (nt * 8 + g) * 80 + koff);
                #pragma unroll
                for (int mt = 0; mt < 4; mt++)
                    mma16(acc[mt][nt], a_lo[mt].x, a_hi[mt].x,
                          a_lo[mt].y, a_hi[mt].y, b2.x, b2.y);
            }
        }
        __syncthreads();
    }

    const int bb_i = cm >> 12;
    #pragma unroll
    for (int mt = 0; mt < 4; mt++) {
        const int row0 = cm + wm * 64 + mt * 16 + g;
        #pragma unroll
        for (int nt = 0; nt < 8; nt++) {
            const int col = cn + wn * 64 + nt * 8 + (tig << 1);
            const float bi0 = bias[col], bi1 = bias[col + 1];
            float v0 = acc[mt][nt][0] + bi0;
            float v1 = acc[mt][nt][1] + bi1;
            float v2 = acc[mt][nt][2] + bi0;
            float v3 = acc[mt][nt][3] + bi1;
            if (MODE == 1) {
                v0 = gelu_tanh(v0); v1 = gelu_tanh(v1);
                v2 = gelu_tanh(v2); v3 = gelu_tanh(v3);
                const int p = permc(col);
                *(half2*)(Ch + (size_t)row0 * N + p)       = __floats2half2_rn(v0, v1);
                *(half2*)(Ch + (size_t)(row0 + 8) * N + p) = __floats2half2_rn(v2, v3);
            } else if (MODE == 3) {
                *(half2*)(Ch + (size_t)row0 * N + col)       = __floats2half2_rn(v0, v1);
                *(half2*)(Ch + (size_t)(row0 + 8) * N + col) = __floats2half2_rn(v2, v3);
            } else {
                if (MODE == 2) {
                    const float g0 = gate[bb_i * 6144 + col];
                    const float g1 = gate[bb_i * 6144 + col + 1];
                    const float2 r0 = *(const float2*)(res + (size_t)row0 * N + col);
                    const float2 r1 = *(const float2*)(res + (size_t)(row0 + 8) * N + col);
                    v0 = r0.x + g0 * v0;  v1 = r0.y + g1 * v1;
                    v2 = r1.x + g0 * v2;  v3 = r1.y + g1 * v3;
                }
                *(float2*)(C + (size_t)row0 * N + col)       = make_float2(v0, v1);
                *(float2*)(C + (size_t)(row0 + 8) * N + col) = make_float2(v2, v3);
            }
        }
    }
}

// ---------------------------------------------------------------------------
// Kernel 5: windowed attention, fp16 mma + ldmatrix, P in registers.
//   One block per (window, head). Q/K/V natural [128][136] fp16 smem.
// ---------------------------------------------------------------------------
#define ATT_STR 136
#define ATTN_SMEM_BYTES (3 * 128 * ATT_STR * 2)

__global__ void __launch_bounds__(256) attn_kernel(
    const __half* __restrict__ qkv, __half* __restrict__ obuf,
    const float2* __restrict__ rope)
{
    extern __shared__ __half sha[];
    __half* Qs = sha;
    __half* Ks = sha + 128 * ATT_STR;
    __half* Vs = sha + 2 * 128 * ATT_STR;
    const uint32_t qs_u = smem_u32(Qs);
    const uint32_t ks_u = smem_u32(Ks);
    const uint32_t vs_u = smem_u32(Vs);

    const int tid  = threadIdx.x;
    const int lane = tid & 31, warp = tid >> 5;
    const int tig  = lane & 3;
    const int h    = blockIdx.x & 7;
    const int w    = blockIdx.x >> 3;
    const size_t rowbase = (size_t)w * 128;

    // load Q,K (rope) and V, all natural fp16
    for (int idx = tid; idx < 8192; idx += 256) {
        const int i  = idx >> 6, dp = idx & 63;
        const int d  = dp << 1;
        const int dr = (d < 64) ? d + 64 : d - 64;
        const float sgn = (d < 64) ? -1.f : 1.f;
        const __half* base = qkv + (rowbase + i) * 3072 + h * 128;
        const float2 sc = rope[i * 64 + dp];

        const float2 qv = __half22float2(*(const half2*)(base + d));
        const float2 qr = __half22float2(*(const half2*)(base + dr));
        *(half2*)(Qs + i * ATT_STR + d) =
            __floats2half2_rn(qv.x * sc.y + sgn * qr.x * sc.x,
                              qv.y * sc.y + sgn * qr.y * sc.x);
        const float2 kv = __half22float2(*(const half2*)(base + 1024 + d));
        const float2 kr = __half22float2(*(const half2*)(base + 1024 + dr));
        *(half2*)(Ks + i * ATT_STR + d) =
            __floats2half2_rn(kv.x * sc.y + sgn * kr.x * sc.x,
                              kv.y * sc.y + sgn * kr.y * sc.x);
        *(half2*)(Vs + i * ATT_STR + d) = *(const half2*)(base + 2048 + d);
    }
    __syncthreads();

    const int m0 = warp * 16;
    // ldmatrix lane-address components
    const int l7  = lane & 7;
    const int a_row = m0 + l7 + ((lane & 8) ? 8 : 0);      // A: +8 rows on bit3
    const int a_kof = (lane & 16) ? 8 : 0;                 // A: +8 k on bit4
    const int b_row = l7 + ((lane & 16) ? 8 : 0);          // K/B: +8 n on bit4
    const int b_kof = (lane & 8) ? 8 : 0;                  // K/B: +8 k on bit3
    const int v_row = l7 + ((lane & 8) ? 8 : 0);           // V: +8 j on bit3
    const int v_dof = (lane & 16) ? 8 : 0;                 // V: +8 d on bit4

    // ---- scores: S = Q K^T ----
    float acc[16][4];
    #pragma unroll
    for (int nt = 0; nt < 16; nt++)
        #pragma unroll
        for (int i = 0; i < 4; i++) acc[nt][i] = 0.f;

    #pragma unroll
    for (int kc = 0; kc < 8; kc++) {
        const int k0 = kc << 4;
        uint32_t a0, a1, a2, a3;
        ldsm_x4(a0, a1, a2, a3, qs_u + (a_row * ATT_STR + k0 + a_kof) * 2);
        #pragma unroll
        for (int np = 0; np < 8; np++) {
            uint32_t b0, b1, c0, c1;
            ldsm_x4(b0, b1, c0, c1,
                    ks_u + ((np * 16 + b_row) * ATT_STR + k0 + b_kof) * 2);
            mma16(acc[2 * np],     a0, a1, a2, a3, b0, b1);
            mma16(acc[2 * np + 1], a0, a1, a2, a3, c0, c1);
        }
    }

    // ---- softmax (rows m0+g and m0+g+8) ----
    const float scl = 0.08838834764831845f;   // 1/sqrt(128)
    float mx0 = -1e30f, mx1 = -1e30f;
    #pragma unroll
    for (int nt = 0; nt < 16; nt++) {
        acc[nt][0] *= scl; acc[nt][1] *= scl; acc[nt][2] *= scl; acc[nt][3] *= scl;
        mx0 = fmaxf(mx0, fmaxf(acc[nt][0], acc[nt][1]));
        mx1 = fmaxf(mx1, fmaxf(acc[nt][2], acc[nt][3]));
    }
    mx0 = fmaxf(mx0, __shfl_xor_sync(0xffffffffu, mx0, 1));
    mx0 = fmaxf(mx0, __shfl_xor_sync(0xffffffffu, mx0, 2));
    mx1 = fmaxf(mx1, __shfl_xor_sync(0xffffffffu, mx1, 1));
    mx1 = fmaxf(mx1, __shfl_xor_sync(0xffffffffu, mx1, 2));

    float s0 = 0.f, s1 = 0.f;
    #pragma unroll
    for (int nt = 0; nt < 16; nt++) {
        acc[nt][0] = __expf(acc[nt][0] - mx0);
        acc[nt][1] = __expf(acc[nt][1] - mx0);
        acc[nt][2] = __expf(acc[nt][2] - mx1);
        acc[nt][3] = __expf(acc[nt][3] - mx1);
        s0 += acc[nt][0] + acc[nt][1];
        s1 += acc[nt][2] + acc[nt][3];
    }
    s0 += __shfl_xor_sync(0xffffffffu, s0, 1);
    s0 += __shfl_xor_sync(0xffffffffu, s0, 2);
    s1 += __shfl_xor_sync(0xffffffffu, s1, 1);
    s1 += __shfl_xor_sync(0xffffffffu, s1, 2);
    const float i0 = 1.f / s0, i1 = 1.f / s1;

    // ---- O = P V  (P frags built in registers from acc) ----
    float o[16][4];
    #pragma unroll
    for (int nt = 0; nt < 16; nt++)
        #pragma unroll
        for (int i = 0; i < 4; i++) o[nt][i] = 0.f;

    #pragma unroll
    for (int kc = 0; kc < 8; kc++) {
        const uint32_t a0 = h2u(
            __floats2half2_rn(acc[2 * kc][0] * i0, acc[2 * kc][1] * i0));
        const uint32_t a1 = h2u(
            __floats2half2_rn(acc[2 * kc][2] * i1, acc[2 * kc][3] * i1));
        const uint32_t a2 = h2u(
            __floats2half2_rn(acc[2 * kc + 1][0] * i0, acc[2 * kc + 1][1] * i0));
        const uint32_t a3 = h2u(
            __floats2half2_rn(acc[2 * kc + 1][2] * i1, acc[2 * kc + 1][3] * i1));
        const int j0 = kc << 4;
        #pragma unroll
        for (int dp = 0; dp < 8; dp++) {
            uint32_t b0, b1, c0, c1;
            ldsm_x4t(b0, b1, c0, c1,
                     vs_u + ((j0 + v_row) * ATT_STR + dp * 16 + v_dof) * 2);
            mma16(o[2 * dp],     a0, a1, a2, a3, b0, b1);
            mma16(o[2 * dp + 1], a0, a1, a2, a3, c0, c1);
        }
    }

    // ---- store O as fp16 permuted (next GEMM's A operand) ----
    const int gq = lane >> 2;
    #pragma unroll
    for (int nt = 0; nt < 16; nt++) {
        const int col = h * 128 + nt * 8 + (tig << 1);
        const int p = permc(col);
        *(half2*)(obuf + (rowbase + m0 + gq) * 1024 + p) =
            __floats2half2_rn(o[nt][0], o[nt][1]);
        *(half2*)(obuf + (rowbase + m0 + gq + 8) * 1024 + p) =
            __floats2half2_rn(o[nt][2], o[nt][3]);
    }
}

// ---------------------------------------------------------------------------
// host launcher
// ---------------------------------------------------------------------------
extern "C" void kernel_launch(void* const* d_in, const int* in_sizes, int n_in,
                              void* d_out, int out_size)
{
    const float* group_x = (const float*)d_in[0];
    const float* context = (const float*)d_in[1];
    const float* W_ada   = (const float*)d_in[2];
    const float* b_ada   = (const float*)d_in[3];
    const float* scale1  = (const float*)d_in[4];
    const float* W_qkv   = (const float*)d_in[5];
    const float* b_qkv   = (const float*)d_in[6];
    const float* W_out   = (const float*)d_in[7];
    const float* b_out   = (const float*)d_in[8];
    const float* scale2  = (const float*)d_in[9];
    const float* W_ff1   = (const float*)d_in[10];
    const float* b_ff1   = (const float*)d_in[11];
    const float* W_ff2   = (const float*)d_in[12];
    const float* b_ff2   = (const float*)d_in[13];
    float* out = (float*)d_out;

    float *ada, *res2;
    __half *x1, *qkv, *obuf, *hbuf, *h1, *wqkv, *wout, *wff1, *wff2;
    float2* rope;
    cudaGetSymbolAddress((void**)&ada,  g_ada);
    cudaGetSymbolAddress((void**)&x1,   g_x1);
    cudaGetSymbolAddress((void**)&qkv,  g_qkv);
    cudaGetSymbolAddress((void**)&obuf, g_o);
    cudaGetSymbolAddress((void**)&res2, g_res);
    cudaGetSymbolAddress((void**)&hbuf, g_h);
    cudaGetSymbolAddress((void**)&h1,   g_h1);
    cudaGetSymbolAddress((void**)&rope, g_rope);
    cudaGetSymbolAddress((void**)&wqkv, g_wqkv);
    cudaGetSymbolAddress((void**)&wout, g_wout);
    cudaGetSymbolAddress((void**)&wff1, g_wff1);
    cudaGetSymbolAddress((void**)&wff2, g_wff2);

    cudaFuncSetAttribute(gemm_fp16<1>, cudaFuncAttributeMaxDynamicSharedMemorySize, GEMM_SMEM);
    cudaFuncSetAttribute(gemm_fp16<2>, cudaFuncAttributeMaxDynamicSharedMemorySize, GEMM_SMEM);
    cudaFuncSetAttribute(gemm_fp16<3>, cudaFuncAttributeMaxDynamicSharedMemorySize, GEMM_SMEM);
    cudaFuncSetAttribute(attn_kernel,  cudaFuncAttributeMaxDynamicSharedMemorySize, ATTN_SMEM_BYTES);

    const dim3 tb(32, 8);
    transpose_round<<<dim3(3072 / 32, 1024 / 32), tb>>>(W_qkv, wqkv, 1024, 3072);
    transpose_round<<<dim3(1024 / 32, 1024 / 32), tb>>>(W_out, wout, 1024, 1024);
    transpose_round<<<dim3(4096 / 32, 1024 / 32), tb>>>(W_ff1, wff1, 1024, 4096);
    transpose_round<<<dim3(1024 / 32, 4096 / 32), tb>>>(W_ff2, wff2, 4096, 1024);

    ada_kernel<<<24, 256>>>(context, W_ada, b_ada, ada);
    rope_kernel<<<32, 256>>>(rope);
    norm_mod<<<32768, 256>>>(group_x, scale1, ada, 0, 1024, x1);

    // qkv = x1 @ W_qkv + b_qkv -> fp16 natural   (N=3072, K=1024)
    gemm_fp16<3><<<dim3(24, 128), 256, GEMM_SMEM>>>(x1, wqkv, b_qkv, nullptr, qkv,
                                                    3072, 1024, nullptr, nullptr);
    attn_kernel<<<2048, 256, ATTN_SMEM_BYTES>>>(qkv, obuf, rope);

    // res2 = group_x + g_msa * (obuf @ W_out + b_out)   (N=1024, K=1024)
    gemm_fp16<2><<<dim3(8, 128), 256, GEMM_SMEM>>>(obuf, wout, b_out, res2, nullptr,
                                                   1024, 1024, group_x, ada + 2048);
    norm_mod<<<32768, 256>>>(res2, scale2, ada, 3072, 4096, hbuf);

    // h1 = gelu(hbuf @ W_ff1 + b_ff1) -> fp16 perm  (N=4096, K=1024)
    gemm_fp16<1><<<dim3(32, 128), 256, GEMM_SMEM>>>(hbuf, wff1, b_ff1, nullptr, h1,
                                                    4096, 1024, nullptr, nullptr);
    // out = res2 + g_mlp * (h1 @ W_ff2 + b_ff2)     (N=1024, K=4096)
    gemm_fp16<2><<<dim3(8, 128), 256, GEMM_SMEM>>>(h1, wff2, b_ff2, out, nullptr,
                                                   1024, 4096, res2, ada + 5120);
}

// round 7
// speedup vs baseline: 1.9669x; 1.0449x over previous
#include <cuda_runtime.h>
#include <cuda_fp16.h>
#include <cstdint>

// ---------------------------------------------------------------------------
// B=8, L=4096, D=1024, H=8, DH=128, WIN=128; M = 32768.
// GEMMs: mma.sync m16n8k16 fp16, perm64 operand layout (one 16B chunk per
// thread per 32-k superblock), XOR-swizzled smem, 3-stage cp.async pipeline.
// Attention: fp16 mma + ldmatrix, cp.async staging, in-smem rope.
// ---------------------------------------------------------------------------

__device__ float  g_ada [8 * 6144];
__device__ __half g_x1  [33554432];    // norm1 output (fp16, perm64)
__device__ __half g_qkv [100663296];   // qkv (fp16, natural)
__device__ __half g_o   [33554432];    // attention out (fp16, perm64)
__device__ float  g_res [33554432];    // residual after MSA (fp32)
__device__ __half g_h   [33554432];    // norm2 output (fp16, perm64)
__device__ __half g_h1  [134217728];   // ff hidden (fp16, perm64)
__device__ float2 g_rope[8192];
__device__ __half g_wqkv[3145728];
__device__ __half g_wout[1048576];
__device__ __half g_wff1[4194304];
__device__ __half g_wff2[4194304];

// ---------------------------------------------------------------------------
// helpers
// ---------------------------------------------------------------------------
__device__ __forceinline__ float gelu_tanh(float x) {
    float u = 0.7978845608028654f * (x + 0.044715f * x * x * x);
    return 0.5f * x * (1.f + tanhf(u));
}

__device__ __forceinline__ uint32_t smem_u32(const void* p) {
    uint32_t a;
    asm("{ .reg .u64 t; cvta.to.shared.u64 t, %1; cvt.u32.u64 %0, t; }" : "=r"(a) : "l"(p));
    return a;
}

__device__ __forceinline__ uint32_t h2u(half2 h) {
    uint32_t u;
    memcpy(&u, &h, 4);
    return u;
}

// perm64: within each 64-half k-block, chunk (tig*2+sb) holds thread tig's
// fragments for superblock sb (2 k-steps). Applied to BOTH A and B k-dims.
__device__ __forceinline__ int perm64h(int k) {
    const int base  = k & ~63;
    const int sb    = (k >> 5) & 1;
    const int b16   = (k >> 4) & 1;
    const int j     = (k & 15) >> 1;
    const int owner = j & 3, hi = j >> 2;
    return base + (owner * 2 + sb) * 8 + b16 * 4 + hi * 2 + (k & 1);
}
// even-pair variant: (col, col+1) -> (p, p+1)
__device__ __forceinline__ int perm64c(int col) { return perm64h(col); }

__device__ __forceinline__ void mma16(float* d, uint32_t a0, uint32_t a1,
                                      uint32_t a2, uint32_t a3,
                                      uint32_t b0, uint32_t b1) {
    asm volatile(
        "mma.sync.aligned.m16n8k16.row.col.f32.f16.f16.f32 "
        "{%0,%1,%2,%3}, {%4,%5,%6,%7}, {%8,%9}, {%0,%1,%2,%3};"
        : "+f"(d[0]), "+f"(d[1]), "+f"(d[2]), "+f"(d[3])
        : "r"(a0), "r"(a1), "r"(a2), "r"(a3), "r"(b0), "r"(b1));
}

__device__ __forceinline__ void ldsm_x4(uint32_t& r0, uint32_t& r1,
                                        uint32_t& r2, uint32_t& r3, uint32_t a) {
    asm volatile("ldmatrix.sync.aligned.m8n8.x4.shared.b16 {%0,%1,%2,%3}, [%4];"
                 : "=r"(r0), "=r"(r1), "=r"(r2), "=r"(r3) : "r"(a));
}
__device__ __forceinline__ void ldsm_x4t(uint32_t& r0, uint32_t& r1,
                                         uint32_t& r2, uint32_t& r3, uint32_t a) {
    asm volatile("ldmatrix.sync.aligned.m8n8.x4.trans.shared.b16 {%0,%1,%2,%3}, [%4];"
                 : "=r"(r0), "=r"(r1), "=r"(r2), "=r"(r3) : "r"(a));
}

__device__ __forceinline__ uint4 lds128(uint32_t a) {
    uint4 v;
    asm volatile("ld.shared.v4.u32 {%0,%1,%2,%3}, [%4];"
                 : "=r"(v.x), "=r"(v.y), "=r"(v.z), "=r"(v.w) : "r"(a));
    return v;
}

__device__ __forceinline__ void cp16(uint32_t dst, const void* src) {
    asm volatile("cp.async.cg.shared.global [%0], [%1], 16;" :: "r"(dst), "l"(src));
}
#define CP_COMMIT() asm volatile("cp.async.commit_group;" ::: "memory")
#define CP_WAIT1()  asm volatile("cp.async.wait_group 1;"  ::: "memory")
#define CP_WAIT0()  asm volatile("cp.async.wait_group 0;"  ::: "memory")

// ---------------------------------------------------------------------------
// Kernel 0: Wt[n][perm64(k)] = fp16(W[k][n])
// ---------------------------------------------------------------------------
__global__ void __launch_bounds__(256) transpose_round(
    const float* __restrict__ W, __half* __restrict__ Wt, int K, int N)
{
    __shared__ float t[32][33];
    const int kb = blockIdx.y * 32, nb = blockIdx.x * 32;
    const int tx = threadIdx.x, ty = threadIdx.y;   // 32 x 8
    #pragma unroll
    for (int i = 0; i < 4; i++)
        t[ty + 8 * i][tx] = W[(size_t)(kb + ty + 8 * i) * N + nb + tx];
    __syncthreads();
    #pragma unroll
    for (int i = 0; i < 4; i++)
        Wt[(size_t)(nb + ty + 8 * i) * K + perm64h(kb + tx)] =
            __float2half_rn(t[tx][ty + 8 * i]);
}

// ---------------------------------------------------------------------------
// Kernel 1: ada = silu(context) @ W_ada + b_ada
// ---------------------------------------------------------------------------
__global__ void __launch_bounds__(256) ada_kernel(
    const float* __restrict__ ctx, const float* __restrict__ W,
    const float* __restrict__ bias, float* __restrict__ ada)
{
    __shared__ float sctx[8 * 1024];
    for (int i = threadIdx.x; i < 8192; i += 256) {
        float c = ctx[i];
        sctx[i] = c / (1.f + __expf(-c));
    }
    __syncthreads();
    const int col = blockIdx.x * 256 + threadIdx.x;
    float acc[8] = {0, 0, 0, 0, 0, 0, 0, 0};
    for (int k = 0; k < 1024; k++) {
        float w = W[(size_t)k * 6144 + col];
        #pragma unroll
        for (int b = 0; b < 8; b++) acc[b] += sctx[b * 1024 + k] * w;
    }
    float bv = bias[col];
    #pragma unroll
    for (int b = 0; b < 8; b++) ada[b * 6144 + col] = acc[b] + bv;
}

// ---------------------------------------------------------------------------
// Kernel 2: rope table
// ---------------------------------------------------------------------------
__global__ void rope_kernel(float2* __restrict__ tab)
{
    int idx = blockIdx.x * 256 + threadIdx.x;
    if (idx < 8192) {
        int pos = idx >> 6;
        int i   = idx & 63;
        float freq = powf(10000.f, -(float)(2 * i) / 128.f);
        float ang  = (float)pos * freq;
        tab[idx] = make_float2(sinf(ang), cosf(ang));
    }
}

// ---------------------------------------------------------------------------
// Kernel 3: rmsnorm + modulate -> fp16 perm64
// ---------------------------------------------------------------------------
__global__ void __launch_bounds__(256) norm_mod(
    const float* __restrict__ x, const float* __restrict__ scale,
    const float* __restrict__ ada, int shOff, int scOff,
    __half* __restrict__ y)
{
    const int row = blockIdx.x;
    const int b   = row >> 12;
    const float4 v = ((const float4*)(x + (size_t)row * 1024))[threadIdx.x];

    float ss = v.x * v.x + v.y * v.y + v.z * v.z + v.w * v.w;
    #pragma unroll
    for (int o = 16; o > 0; o >>= 1) ss += __shfl_xor_sync(0xffffffffu, ss, o);
    __shared__ float ws[8];
    if ((threadIdx.x & 31) == 0) ws[threadIdx.x >> 5] = ss;
    __syncthreads();
    float tot = 0.f;
    #pragma unroll
    for (int i = 0; i < 8; i++) tot += ws[i];
    const float r = rsqrtf(tot * (1.f / 1024.f) + 1e-5f);

    const int c = threadIdx.x * 4;
    const float* ab = ada + b * 6144;
    const float4 s   = *(const float4*)(scale + c);
    const float4 sh  = *(const float4*)(ab + shOff + c);
    const float4 scm = *(const float4*)(ab + scOff + c);
    float o0 = v.x * r * s.x * (1.f + scm.x) + sh.x;
    float o1 = v.y * r * s.y * (1.f + scm.y) + sh.y;
    float o2 = v.z * r * s.z * (1.f + scm.z) + sh.z;
    float o3 = v.w * r * s.w * (1.f + scm.w) + sh.w;
    __half* yr = y + (size_t)row * 1024;
    *(half2*)(yr + perm64c(c))     = __floats2half2_rn(o0, o1);
    *(half2*)(yr + perm64c(c + 2)) = __floats2half2_rn(o2, o3);
}

// ---------------------------------------------------------------------------
// Kernel 4: fp16 GEMM, C[M,N] = A[M,K] @ Bt[N,K]^T  (+epilogue)
//   CTA 256x128, BK=64, 8 warps of 64x64. perm64 operands, smem rows = 128B
//   exact with chunk^(row&7) XOR swizzle (conflict-free LDS.128 / STS.128).
//   3-stage cp.async pipeline, one __syncthreads per k-tile.
//   MODE 0: fp32. 1: fp16-perm64 gelu. 2: fp32 res+gate*C. 3: fp16 natural.
// ---------------------------------------------------------------------------
#define STAGE_BYTES 49152            // A: 256*128 + B: 128*128
#define GEMM_SMEM  (3 * STAGE_BYTES)

template <int MODE>
__global__ void __launch_bounds__(256, 1) gemm_fp16(
    const __half* __restrict__ A, const __half* __restrict__ Bt,
    const float* __restrict__ bias,
    float* __restrict__ C, __half* __restrict__ Ch,
    int N, int K,
    const float* __restrict__ res, const float* __restrict__ gate)
{
    extern __shared__ char smem[];
    const uint32_t sm_u = smem_u32(smem);

    const int tid  = threadIdx.x;
    const int lane = tid & 31;
    const int warp = tid >> 5;
    const int g    = lane >> 2, tig = lane & 3;
    const int wm   = warp & 3;
    const int wn   = warp >> 2;
    const int cm   = blockIdx.y << 8;
    const int cn   = blockIdx.x << 7;
    const int KT   = K >> 6;

    // staging thread mapping: chunk c -> row = c>>3, ch = c&7 (8 chunks/row)
    const int f_row = tid >> 3;
    const int f_ch  = tid & 7;

    auto fill = [&](int kt, int s) {
        const uint32_t sb_ = sm_u + s * STAGE_BYTES;
        const __half* Ag = A + (size_t)(cm + f_row) * K + (kt << 6) + f_ch * 8;
        #pragma unroll
        for (int i = 0; i < 8; i++) {
            const int row = f_row + i * 32;
            cp16(sb_ + row * 128 + ((f_ch ^ (row & 7)) << 4),
                 Ag + (size_t)i * 32 * K);
        }
        const __half* Bg = Bt + (size_t)(cn + f_row) * K + (kt << 6) + f_ch * 8;
        #pragma unroll
        for (int i = 0; i < 4; i++) {
            const int row = f_row + i * 32;
            cp16(sb_ + 32768 + row * 128 + ((f_ch ^ (row & 7)) << 4),
                 Bg + (size_t)i * 32 * K);
        }
    };

    float acc[4][8][4];
    #pragma unroll
    for (int mt = 0; mt < 4; mt++)
        #pragma unroll
        for (int nt = 0; nt < 8; nt++)
            #pragma unroll
            for (int i = 0; i < 4; i++) acc[mt][nt][i] = 0.f;

    fill(0, 0); CP_COMMIT();
    if (KT > 1) fill(1, 1);
    CP_COMMIT();

    int s = 0;
    for (int kt = 0; kt < KT; kt++) {
        CP_WAIT1();
        __syncthreads();

        const uint32_t a_base = sm_u + s * STAGE_BYTES;
        const uint32_t b_base = a_base + 32768;
        #pragma unroll
        for (int sb = 0; sb < 2; sb++) {
            const int chn = (tig << 1) | sb;
            uint4 al[4], ah[4];
            #pragma unroll
            for (int mt = 0; mt < 4; mt++) {
                const int rl = wm * 64 + mt * 16 + g;
                al[mt] = lds128(a_base + rl * 128 + ((chn ^ (rl & 7)) << 4));
                ah[mt] = lds128(a_base + (rl + 8) * 128 + ((chn ^ (rl & 7)) << 4));
            }
            #pragma unroll
            for (int nt = 0; nt < 8; nt++) {
                const int rb = wn * 64 + nt * 8 + g;
                const uint4 bb = lds128(b_base + rb * 128 + ((chn ^ (rb & 7)) << 4));
                #pragma unroll
                for (int mt = 0; mt < 4; mt++) {
                    mma16(acc[mt][nt], al[mt].x, ah[mt].x, al[mt].y, ah[mt].y,
                          bb.x, bb.y);
                    mma16(acc[mt][nt], al[mt].z, ah[mt].z, al[mt].w, ah[mt].w,
                          bb.z, bb.w);
                }
            }
        }
        if (kt + 2 < KT) fill(kt + 2, (s + 2 >= 3) ? s - 1 : s + 2);
        CP_COMMIT();   // empty group OK: keeps wait_group 1 == "stage done"
        s = (s + 1 == 3) ? 0 : s + 1;
    }

    const int bb_i = cm >> 12;
    #pragma unroll
    for (int mt = 0; mt < 4; mt++) {
        const int row0 = cm + wm * 64 + mt * 16 + g;
        #pragma unroll
        for (int nt = 0; nt < 8; nt++) {
            const int col = cn + wn * 64 + nt * 8 + (tig << 1);
            const float bi0 = bias[col], bi1 = bias[col + 1];
            float v0 = acc[mt][nt][0] + bi0;
            float v1 = acc[mt][nt][1] + bi1;
            float v2 = acc[mt][nt][2] + bi0;
            float v3 = acc[mt][nt][3] + bi1;
            if (MODE == 1) {
                v0 = gelu_tanh(v0); v1 = gelu_tanh(v1);
                v2 = gelu_tanh(v2); v3 = gelu_tanh(v3);
                const int p = perm64c(col);
                *(half2*)(Ch + (size_t)row0 * N + p)       = __floats2half2_rn(v0, v1);
                *(half2*)(Ch + (size_t)(row0 + 8) * N + p) = __floats2half2_rn(v2, v3);
            } else if (MODE == 3) {
                *(half2*)(Ch + (size_t)row0 * N + col)       = __floats2half2_rn(v0, v1);
                *(half2*)(Ch + (size_t)(row0 + 8) * N + col) = __floats2half2_rn(v2, v3);
            } else {
                if (MODE == 2) {
                    const float g0 = gate[bb_i * 6144 + col];
                    const float g1 = gate[bb_i * 6144 + col + 1];
                    const float2 r0 = *(const float2*)(res + (size_t)row0 * N + col);
                    const float2 r1 = *(const float2*)(res + (size_t)(row0 + 8) * N + col);
                    v0 = r0.x + g0 * v0;  v1 = r0.y + g1 * v1;
                    v2 = r1.x + g0 * v2;  v3 = r1.y + g1 * v3;
                }
                *(float2*)(C + (size_t)row0 * N + col)       = make_float2(v0, v1);
                *(float2*)(C + (size_t)(row0 + 8) * N + col) = make_float2(v2, v3);
            }
        }
    }
}

// ---------------------------------------------------------------------------
// Kernel 5: windowed attention. cp.async staging of raw Q/K/V, rope applied
// in-smem, then fp16 mma + ldmatrix with P kept in registers.
// ---------------------------------------------------------------------------
#define ATT_STR 136
#define ATTN_SMEM_BYTES (3 * 128 * ATT_STR * 2)

__global__ void __launch_bounds__(256) attn_kernel(
    const __half* __restrict__ qkv, __half* __restrict__ obuf,
    const float2* __restrict__ rope)
{
    extern __shared__ __half sha[];
    __half* Qs = sha;
    __half* Ks = sha + 128 * ATT_STR;
    __half* Vs = sha + 2 * 128 * ATT_STR;
    const uint32_t qs_u = smem_u32(Qs);
    const uint32_t ks_u = smem_u32(Ks);
    const uint32_t vs_u = smem_u32(Vs);

    const int tid  = threadIdx.x;
    const int lane = tid & 31, warp = tid >> 5;
    const int tig  = lane & 3;
    const int h    = blockIdx.x & 7;
    const int w    = blockIdx.x >> 3;
    const size_t rowbase = (size_t)w * 128;

    // ---- stage raw Q/K/V via cp.async (16 chunks of 16B per 128-half row) --
    {
        const int row = tid >> 4, ch = tid & 15;
        const __half* base = qkv + (rowbase + row) * 3072 + h * 128 + ch * 8;
        #pragma unroll
        for (int i = 0; i < 8; i++) {
            const uint32_t off = (row + i * 16) * (ATT_STR * 2) + ch * 16;
            const __half* src = base + (size_t)i * 16 * 3072;
            cp16(qs_u + off, src);
            cp16(ks_u + off, src + 1024);
            cp16(vs_u + off, src + 2048);
        }
    }
    CP_COMMIT(); CP_WAIT0();
    __syncthreads();

    // ---- rope in place on Q and K (each thread owns both rotation partners)
    #pragma unroll
    for (int t = 0; t < 16; t++) {
        const int task = tid + t * 256;        // 4096 tasks: 128 rows x 32 dp
        const int i  = task >> 5;
        const int dp = task & 31;              // half2 index in [0,32)
        const int d  = dp << 1;                // 0..62 (first half)
        const float2 sc_lo = rope[i * 64 + dp];
        const float2 sc_hi = rope[i * 64 + dp + 32];
        {
            float2 a = __half22float2(*(half2*)(Qs + i * ATT_STR + d));
            float2 b = __half22float2(*(half2*)(Qs + i * ATT_STR + d + 64));
            *(half2*)(Qs + i * ATT_STR + d) =
                __floats2half2_rn(a.x * sc_lo.y - b.x * sc_lo.x,
                                  a.y * sc_lo.y - b.y * sc_lo.x);
            *(half2*)(Qs + i * ATT_STR + d + 64) =
                __floats2half2_rn(b.x * sc_hi.y + a.x * sc_hi.x,
                                  b.y * sc_hi.y + a.y * sc_hi.x);
        }
        {
            float2 a = __half22float2(*(half2*)(Ks + i * ATT_STR + d));
            float2 b = __half22float2(*(half2*)(Ks + i * ATT_STR + d + 64));
            *(half2*)(Ks + i * ATT_STR + d) =
                __floats2half2_rn(a.x * sc_lo.y - b.x * sc_lo.x,
                                  a.y * sc_lo.y - b.y * sc_lo.x);
            *(half2*)(Ks + i * ATT_STR + d + 64) =
                __floats2half2_rn(b.x * sc_hi.y + a.x * sc_hi.x,
                                  b.y * sc_hi.y + a.y * sc_hi.x);
        }
    }
    __syncthreads();

    const int m0 = warp * 16;
    const int l7  = lane & 7;
    const int a_row = m0 + l7 + ((lane & 8) ? 8 : 0);
    const int a_kof = (lane & 16) ? 8 : 0;
    const int b_row = l7 + ((lane & 16) ? 8 : 0);
    const int b_kof = (lane & 8) ? 8 : 0;
    const int v_row = l7 + ((lane & 8) ? 8 : 0);
    const int v_dof = (lane & 16) ? 8 : 0;

    // ---- scores: S = Q K^T ----
    float acc[16][4];
    #pragma unroll
    for (int nt = 0; nt < 16; nt++)
        #pragma unroll
        for (int i = 0; i < 4; i++) acc[nt][i] = 0.f;

    #pragma unroll
    for (int kc = 0; kc < 8; kc++) {
        const int k0 = kc << 4;
        uint32_t a0, a1, a2, a3;
        ldsm_x4(a0, a1, a2, a3, qs_u + (a_row * ATT_STR + k0 + a_kof) * 2);
        #pragma unroll
        for (int np = 0; np < 8; np++) {
            uint32_t b0, b1, c0, c1;
            ldsm_x4(b0, b1, c0, c1,
                    ks_u + ((np * 16 + b_row) * ATT_STR + k0 + b_kof) * 2);
            mma16(acc[2 * np],     a0, a1, a2, a3, b0, b1);
            mma16(acc[2 * np + 1], a0, a1, a2, a3, c0, c1);
        }
    }

    // ---- softmax ----
    const float scl = 0.08838834764831845f;
    float mx0 = -1e30f, mx1 = -1e30f;
    #pragma unroll
    for (int nt = 0; nt < 16; nt++) {
        acc[nt][0] *= scl; acc[nt][1] *= scl; acc[nt][2] *= scl; acc[nt][3] *= scl;
        mx0 = fmaxf(mx0, fmaxf(acc[nt][0], acc[nt][1]));
        mx1 = fmaxf(mx1, fmaxf(acc[nt][2], acc[nt][3]));
    }
    mx0 = fmaxf(mx0, __shfl_xor_sync(0xffffffffu, mx0, 1));
    mx0 = fmaxf(mx0, __shfl_xor_sync(0xffffffffu, mx0, 2));
    mx1 = fmaxf(mx1, __shfl_xor_sync(0xffffffffu, mx1, 1));
    mx1 = fmaxf(mx1, __shfl_xor_sync(0xffffffffu, mx1, 2));

    float s0 = 0.f, s1 = 0.f;
    #pragma unroll
    for (int nt = 0; nt < 16; nt++) {
        acc[nt][0] = __expf(acc[nt][0] - mx0);
        acc[nt][1] = __expf(acc[nt][1] - mx0);
        acc[nt][2] = __expf(acc[nt][2] - mx1);
        acc[nt][3] = __expf(acc[nt][3] - mx1);
        s0 += acc[nt][0] + acc[nt][1];
        s1 += acc[nt][2] + acc[nt][3];
    }
    s0 += __shfl_xor_sync(0xffffffffu, s0, 1);
    s0 += __shfl_xor_sync(0xffffffffu, s0, 2);
    s1 += __shfl_xor_sync(0xffffffffu, s1, 1);
    s1 += __shfl_xor_sync(0xffffffffu, s1, 2);
    const float i0 = 1.f / s0, i1 = 1.f / s1;

    // ---- O = P V ----
    float o[16][4];
    #pragma unroll
    for (int nt = 0; nt < 16; nt++)
        #pragma unroll
        for (int i = 0; i < 4; i++) o[nt][i] = 0.f;

    #pragma unroll
    for (int kc = 0; kc < 8; kc++) {
        const uint32_t a0 = h2u(__floats2half2_rn(acc[2 * kc][0] * i0, acc[2 * kc][1] * i0));
        const uint32_t a1 = h2u(__floats2half2_rn(acc[2 * kc][2] * i1, acc[2 * kc][3] * i1));
        const uint32_t a2 = h2u(__floats2half2_rn(acc[2 * kc + 1][0] * i0, acc[2 * kc + 1][1] * i0));
        const uint32_t a3 = h2u(__floats2half2_rn(acc[2 * kc + 1][2] * i1, acc[2 * kc + 1][3] * i1));
        const int j0 = kc << 4;
        #pragma unroll
        for (int dp = 0; dp < 8; dp++) {
            uint32_t b0, b1, c0, c1;
            ldsm_x4t(b0, b1, c0, c1,
                     vs_u + ((j0 + v_row) * ATT_STR + dp * 16 + v_dof) * 2);
            mma16(o[2 * dp],     a0, a1, a2, a3, b0, b1);
            mma16(o[2 * dp + 1], a0, a1, a2, a3, c0, c1);
        }
    }

    // ---- store O as fp16 perm64 ----
    const int gq = lane >> 2;
    #pragma unroll
    for (int nt = 0; nt < 16; nt++) {
        const int col = h * 128 + nt * 8 + (tig << 1);
        const int p = perm64c(col);
        *(half2*)(obuf + (rowbase + m0 + gq) * 1024 + p) =
            __floats2half2_rn(o[nt][0], o[nt][1]);
        *(half2*)(obuf + (rowbase + m0 + gq + 8) * 1024 + p) =
            __floats2half2_rn(o[nt][2], o[nt][3]);
    }
}

// ---------------------------------------------------------------------------
// host launcher
// ---------------------------------------------------------------------------
extern "C" void kernel_launch(void* const* d_in, const int* in_sizes, int n_in,
                              void* d_out, int out_size)
{
    const float* group_x = (const float*)d_in[0];
    const float* context = (const float*)d_in[1];
    const float* W_ada   = (const float*)d_in[2];
    const float* b_ada   = (const float*)d_in[3];
    const float* scale1  = (const float*)d_in[4];
    const float* W_qkv   = (const float*)d_in[5];
    const float* b_qkv   = (const float*)d_in[6];
    const float* W_out   = (const float*)d_in[7];
    const float* b_out   = (const float*)d_in[8];
    const float* scale2  = (const float*)d_in[9];
    const float* W_ff1   = (const float*)d_in[10];
    const float* b_ff1   = (const float*)d_in[11];
    const float* W_ff2   = (const float*)d_in[12];
    const float* b_ff2   = (const float*)d_in[13];
    float* out = (float*)d_out;

    float *ada, *res2;
    __half *x1, *qkv, *obuf, *hbuf, *h1, *wqkv, *wout, *wff1, *wff2;
    float2* rope;
    cudaGetSymbolAddress((void**)&ada,  g_ada);
    cudaGetSymbolAddress((void**)&x1,   g_x1);
    cudaGetSymbolAddress((void**)&qkv,  g_qkv);
    cudaGetSymbolAddress((void**)&obuf, g_o);
    cudaGetSymbolAddress((void**)&res2, g_res);
    cudaGetSymbolAddress((void**)&hbuf, g_h);
    cudaGetSymbolAddress((void**)&h1,   g_h1);
    cudaGetSymbolAddress((void**)&rope, g_rope);
    cudaGetSymbolAddress((void**)&wqkv, g_wqkv);
    cudaGetSymbolAddress((void**)&wout, g_wout);
    cudaGetSymbolAddress((void**)&wff1, g_wff1);
    cudaGetSymbolAddress((void**)&wff2, g_wff2);

    cudaFuncSetAttribute(gemm_fp16<1>, cudaFuncAttributeMaxDynamicSharedMemorySize, GEMM_SMEM);
    cudaFuncSetAttribute(gemm_fp16<2>, cudaFuncAttributeMaxDynamicSharedMemorySize, GEMM_SMEM);
    cudaFuncSetAttribute(gemm_fp16<3>, cudaFuncAttributeMaxDynamicSharedMemorySize, GEMM_SMEM);
    cudaFuncSetAttribute(attn_kernel,  cudaFuncAttributeMaxDynamicSharedMemorySize, ATTN_SMEM_BYTES);

    const dim3 tb(32, 8);
    transpose_round<<<dim3(3072 / 32, 1024 / 32), tb>>>(W_qkv, wqkv, 1024, 3072);
    transpose_round<<<dim3(1024 / 32, 1024 / 32), tb>>>(W_out, wout, 1024, 1024);
    transpose_round<<<dim3(4096 / 32, 1024 / 32), tb>>>(W_ff1, wff1, 1024, 4096);
    transpose_round<<<dim3(1024 / 32, 4096 / 32), tb>>>(W_ff2, wff2, 4096, 1024);

    ada_kernel<<<24, 256>>>(context, W_ada, b_ada, ada);
    rope_kernel<<<32, 256>>>(rope);
    norm_mod<<<32768, 256>>>(group_x, scale1, ada, 0, 1024, x1);

    // qkv = x1 @ W_qkv + b_qkv -> fp16 natural   (N=3072, K=1024)
    gemm_fp16<3><<<dim3(24, 128), 256, GEMM_SMEM>>>(x1, wqkv, b_qkv, nullptr, qkv,
                                                    3072, 1024, nullptr, nullptr);
    attn_kernel<<<2048, 256, ATTN_SMEM_BYTES>>>(qkv, obuf, rope);

    // res2 = group_x + g_msa * (obuf @ W_out + b_out)   (N=1024, K=1024)
    gemm_fp16<2><<<dim3(8, 128), 256, GEMM_SMEM>>>(obuf, wout, b_out, res2, nullptr,
                                                   1024, 1024, group_x, ada + 2048);
    norm_mod<<<32768, 256>>>(res2, scale2, ada, 3072, 4096, hbuf);

    // h1 = gelu(hbuf @ W_ff1 + b_ff1) -> fp16 perm64  (N=4096, K=1024)
    gemm_fp16<1><<<dim3(32, 128), 256, GEMM_SMEM>>>(hbuf, wff1, b_ff1, nullptr, h1,
                                                    4096, 1024, nullptr, nullptr);
    // out = res2 + g_mlp * (h1 @ W_ff2 + b_ff2)        (N=1024, K=4096)
    gemm_fp16<2><<<dim3(8, 128), 256, GEMM_SMEM>>>(h1, wff2, b_ff2, out, nullptr,
                                                   1024, 4096, res2, ada + 5120);
}